// round 1
// baseline (speedup 1.0000x reference)
#include <cuda_runtime.h>
#include <cuda_bf16.h>
#include <math.h>

// Problem constants
#define Bsz 16
#define SEQ 1024
#define HID 1152
#define NH 16
#define HD 72
#define MLPD 4608
#define ROWS (Bsz * SEQ)          // 16384
#define MODW (6 * HID)            // 6912
#define EPS 1e-6f

// ---------------- scratch (device globals; allocation-free) ----------------
__device__ float g_mod[Bsz * MODW];            // adaLN modulation (16 x 6912)
__device__ float g_xn [ROWS * HID];            // normalized/modulated input (reused)
__device__ float g_qkv[ROWS * 3 * HID];        // qkv projection (LN'd q,k in place)
__device__ float g_o  [ROWS * HID];            // attention output (B,N,H)
__device__ float g_x1 [ROWS * HID];            // x after attention residual
__device__ float g_h  [ROWS * MLPD];           // MLP hidden

// ---------------- kernel 1: mod = swish(c) @ w_mod + b_mod ----------------
__global__ __launch_bounds__(128) void mod_kernel(
    const float* __restrict__ c, const float* __restrict__ w_mod,
    const float* __restrict__ b_mod, float* __restrict__ mod)
{
    __shared__ float sc[HID];
    int b = blockIdx.y;
    for (int i = threadIdx.x; i < HID; i += blockDim.x) {
        float v = c[b * HID + i];
        sc[i] = v / (1.0f + expf(-v));
    }
    __syncthreads();
    int col = blockIdx.x * blockDim.x + threadIdx.x;   // 0..6911
    float acc = b_mod[col];
    #pragma unroll 4
    for (int k = 0; k < HID; ++k)
        acc = fmaf(sc[k], w_mod[(size_t)k * MODW + col], acc);
    mod[b * MODW + col] = acc;
}

// --------------- kernel 2: LN(x) * (1+sc) + sh  (per row) ------------------
__global__ __launch_bounds__(256) void ln_mod_kernel(
    const float* __restrict__ x, const float* __restrict__ mod,
    int shOff, int scOff, float* __restrict__ out)
{
    __shared__ float buf[HID];
    __shared__ float red[16];
    int row = blockIdx.x;
    int b = row >> 10;
    int tid = threadIdx.x;
    const float* xr = x + (size_t)row * HID;
    float s = 0.f, s2 = 0.f;
    for (int i = tid; i < HID; i += 256) {
        float v = xr[i];
        buf[i] = v;
        s += v; s2 += v * v;
    }
    #pragma unroll
    for (int o = 16; o; o >>= 1) {
        s  += __shfl_xor_sync(0xffffffffu, s,  o);
        s2 += __shfl_xor_sync(0xffffffffu, s2, o);
    }
    if ((tid & 31) == 0) { red[tid >> 5] = s; red[8 + (tid >> 5)] = s2; }
    __syncthreads();
    float S = 0.f, S2 = 0.f;
    #pragma unroll
    for (int w = 0; w < 8; ++w) { S += red[w]; S2 += red[8 + w]; }
    float mean = S * (1.f / HID);
    float var  = S2 * (1.f / HID) - mean * mean;
    float rstd = rsqrtf(var + EPS);
    const float* mrow = mod + b * MODW;
    float* orow = out + (size_t)row * HID;
    for (int i = tid; i < HID; i += 256) {
        float v = (buf[i] - mean) * rstd;
        orow[i] = fmaf(v, 1.f + mrow[scOff + i], mrow[shOff + i]);
    }
}

// --------------- kernel 3: per-head LN of q and k (in place) ---------------
__global__ __launch_bounds__(256) void qkln_kernel(
    float* __restrict__ qkv, const float* __restrict__ g_q,
    const float* __restrict__ g_k)
{
    int warp = blockIdx.x * 8 + (threadIdx.x >> 5);   // 0 .. 16384*32-1
    int lane = threadIdx.x & 31;
    int h  = warp & 15;
    int qk = (warp >> 4) & 1;
    int bn = warp >> 5;
    float* p = qkv + (size_t)bn * (3 * HID) + qk * HID + h * HD;
    float v0 = p[lane];
    float v1 = p[lane + 32];
    float v2 = (lane < 8) ? p[lane + 64] : 0.f;
    float s  = v0 + v1 + v2;
    float s2 = v0 * v0 + v1 * v1 + v2 * v2;
    #pragma unroll
    for (int o = 16; o; o >>= 1) {
        s  += __shfl_xor_sync(0xffffffffu, s,  o);
        s2 += __shfl_xor_sync(0xffffffffu, s2, o);
    }
    float mean = s * (1.f / HD);
    float var  = s2 * (1.f / HD) - mean * mean;
    float rstd = rsqrtf(var + EPS);
    const float* g = qk ? g_k : g_q;
    p[lane]      = (v0 - mean) * rstd * g[lane];
    p[lane + 32] = (v1 - mean) * rstd * g[lane + 32];
    if (lane < 8) p[lane + 64] = (v2 - mean) * rstd * g[lane + 64];
}

// --------------- kernel 4: flash attention (fp32) --------------------------
// grid (16 q-tiles, NH, B), 256 threads. BQ=64, BK=64.
// thread (tr = tid/16, tc = tid%16): scores 4x4, output 4 q x 5 dims (D padded 80).
#define BQ 64
#define BKT 64
#define QSTR 81           // padded stride for qs/ks/vs
#define PSTR 65           // padded stride for P
#define ATTN_SMEM ((3 * BQ * QSTR + BQ * PSTR) * 4)

__global__ __launch_bounds__(256) void attn_kernel(
    const float* __restrict__ qkv, float* __restrict__ o)
{
    extern __shared__ float sm[];
    float* qs = sm;                       // [64][81]
    float* ks = qs + BQ * QSTR;           // [64][81]
    float* vs = ks + BKT * QSTR;          // [64][81]
    float* P  = vs + BKT * QSTR;          // [64][65]

    int tid = threadIdx.x;
    int tr = tid >> 4, tc = tid & 15;
    int q0 = blockIdx.x * BQ;
    int h = blockIdx.y, b = blockIdx.z;
    const size_t baseBN = (size_t)b * SEQ * (3 * HID);
    const int hoff = h * HD;
    const float scale = 0.11785113019775793f;   // 1/sqrt(72)

    // load q tile
    for (int idx = tid; idx < BQ * HD; idx += 256) {
        int r = idx / HD, d = idx - r * HD;
        qs[r * QSTR + d] = qkv[baseBN + (size_t)(q0 + r) * (3 * HID) + hoff + d];
    }
    // zero v padding cols 72..79 (persist across tiles; loads only touch d<72)
    for (int idx = tid; idx < BKT * 8; idx += 256)
        vs[(idx >> 3) * QSTR + 72 + (idx & 7)] = 0.f;

    float acc[4][5];
    #pragma unroll
    for (int i = 0; i < 4; ++i)
        #pragma unroll
        for (int j = 0; j < 5; ++j) acc[i][j] = 0.f;
    float mi[4] = {-INFINITY, -INFINITY, -INFINITY, -INFINITY};
    float li[4] = {0.f, 0.f, 0.f, 0.f};

    for (int kt = 0; kt < SEQ / BKT; ++kt) {
        __syncthreads();   // prior PV done (and qs/pad on first iter)
        int k0 = kt * BKT;
        for (int idx = tid; idx < BKT * HD; idx += 256) {
            int r = idx / HD, d = idx - r * HD;
            size_t base = baseBN + (size_t)(k0 + r) * (3 * HID) + hoff + d;
            ks[r * QSTR + d] = qkv[base + HID];
            vs[r * QSTR + d] = qkv[base + 2 * HID];
        }
        __syncthreads();

        // ---- scores 4x4 ----
        float sc[4][4];
        #pragma unroll
        for (int i = 0; i < 4; ++i)
            #pragma unroll
            for (int j = 0; j < 4; ++j) sc[i][j] = 0.f;
        for (int d = 0; d < HD; ++d) {
            float qa[4], kb[4];
            #pragma unroll
            for (int i = 0; i < 4; ++i) qa[i] = qs[(tr * 4 + i) * QSTR + d];
            #pragma unroll
            for (int j = 0; j < 4; ++j) kb[j] = ks[(tc * 4 + j) * QSTR + d];
            #pragma unroll
            for (int i = 0; i < 4; ++i)
                #pragma unroll
                for (int j = 0; j < 4; ++j)
                    sc[i][j] = fmaf(qa[i], kb[j], sc[i][j]);
        }
        // ---- online softmax per row ----
        #pragma unroll
        for (int i = 0; i < 4; ++i) {
            float s0 = sc[i][0] * scale, s1 = sc[i][1] * scale;
            float s2 = sc[i][2] * scale, s3 = sc[i][3] * scale;
            float rm = fmaxf(fmaxf(s0, s1), fmaxf(s2, s3));
            #pragma unroll
            for (int off = 8; off; off >>= 1)
                rm = fmaxf(rm, __shfl_xor_sync(0xffffffffu, rm, off));
            float newm = fmaxf(mi[i], rm);
            float p0 = __expf(s0 - newm), p1 = __expf(s1 - newm);
            float p2 = __expf(s2 - newm), p3 = __expf(s3 - newm);
            float ps = p0 + p1 + p2 + p3;
            #pragma unroll
            for (int off = 8; off; off >>= 1)
                ps += __shfl_xor_sync(0xffffffffu, ps, off);
            float alpha = __expf(mi[i] - newm);
            li[i] = li[i] * alpha + ps;
            mi[i] = newm;
            float* pr = P + (tr * 4 + i) * PSTR + tc * 4;
            pr[0] = p0; pr[1] = p1; pr[2] = p2; pr[3] = p3;
            #pragma unroll
            for (int j = 0; j < 5; ++j) acc[i][j] *= alpha;
        }
        __syncwarp();
        // ---- PV: acc[i][j] += P[qi][kj] * v[kj][tc*5+j] ----
        for (int kj = 0; kj < BKT; ++kj) {
            float vv[5];
            #pragma unroll
            for (int j = 0; j < 5; ++j) vv[j] = vs[kj * QSTR + tc * 5 + j];
            #pragma unroll
            for (int i = 0; i < 4; ++i) {
                float pp = P[(tr * 4 + i) * PSTR + kj];
                #pragma unroll
                for (int j = 0; j < 5; ++j)
                    acc[i][j] = fmaf(pp, vv[j], acc[i][j]);
            }
        }
    }
    // ---- write output (B,N,H) layout ----
    #pragma unroll
    for (int i = 0; i < 4; ++i) {
        float inv = 1.f / li[i];
        int n = q0 + tr * 4 + i;
        size_t base = ((size_t)b * SEQ + n) * HID + hoff;
        #pragma unroll
        for (int j = 0; j < 5; ++j) {
            int d = tc * 5 + j;
            if (d < HD) o[base + d] = acc[i][j] * inv;
        }
    }
}

// --------------- kernel 5: SGEMM 128x128x8, 8x8/thread, double-buffered ----
// EPI 0: C = A@B + bias
// EPI 1: C = gelu_tanh(A@B + bias)
// EPI 2: C = res + gate[(row>>10)*6912 + col] * (A@B + bias)
template <int EPI>
__global__ __launch_bounds__(256) void sgemm_kernel(
    const float* __restrict__ A, const float* __restrict__ Bm,
    const float* __restrict__ bias, const float* __restrict__ res,
    const float* __restrict__ gate, float* __restrict__ C,
    int M, int N, int K)
{
    const int BM = 128, BN = 128, BK = 8;
    __shared__ float As[2][BK][BM];
    __shared__ float Bs[2][BK][BN];
    int tid = threadIdx.x;
    int cRow = blockIdx.y, cCol = blockIdx.x;
    const float* Ab = A + (size_t)cRow * BM * K;
    const float* Bb = Bm + cCol * BN;
    int aRow = tid >> 1, aCol = (tid & 1) * 4;
    int bRow = tid >> 5, bCol = (tid & 31) * 4;
    int tr = tid >> 4, tc = tid & 15;

    float acc[8][8];
    #pragma unroll
    for (int i = 0; i < 8; ++i)
        #pragma unroll
        for (int j = 0; j < 8; ++j) acc[i][j] = 0.f;

    float4 a4 = *(const float4*)(Ab + (size_t)aRow * K + aCol);
    float4 b4 = *(const float4*)(Bb + (size_t)bRow * N + bCol);
    As[0][aCol + 0][aRow] = a4.x; As[0][aCol + 1][aRow] = a4.y;
    As[0][aCol + 2][aRow] = a4.z; As[0][aCol + 3][aRow] = a4.w;
    *(float4*)&Bs[0][bRow][bCol] = b4;
    __syncthreads();

    int KT = K / BK;
    for (int kt = 0; kt < KT; ++kt) {
        int cur = kt & 1;
        if (kt + 1 < KT) {
            a4 = *(const float4*)(Ab + (size_t)aRow * K + (kt + 1) * BK + aCol);
            b4 = *(const float4*)(Bb + (size_t)((kt + 1) * BK + bRow) * N + bCol);
        }
        #pragma unroll
        for (int k = 0; k < BK; ++k) {
            float4 ra0 = *(const float4*)&As[cur][k][tr * 8];
            float4 ra1 = *(const float4*)&As[cur][k][tr * 8 + 4];
            float4 rb0 = *(const float4*)&Bs[cur][k][tc * 8];
            float4 rb1 = *(const float4*)&Bs[cur][k][tc * 8 + 4];
            float ra[8] = {ra0.x, ra0.y, ra0.z, ra0.w, ra1.x, ra1.y, ra1.z, ra1.w};
            float rb[8] = {rb0.x, rb0.y, rb0.z, rb0.w, rb1.x, rb1.y, rb1.z, rb1.w};
            #pragma unroll
            for (int i = 0; i < 8; ++i)
                #pragma unroll
                for (int j = 0; j < 8; ++j)
                    acc[i][j] = fmaf(ra[i], rb[j], acc[i][j]);
        }
        if (kt + 1 < KT) {
            int nxt = cur ^ 1;
            As[nxt][aCol + 0][aRow] = a4.x; As[nxt][aCol + 1][aRow] = a4.y;
            As[nxt][aCol + 2][aRow] = a4.z; As[nxt][aCol + 3][aRow] = a4.w;
            *(float4*)&Bs[nxt][bRow][bCol] = b4;
        }
        __syncthreads();
    }

    // epilogue (vectorized stores)
    #pragma unroll
    for (int i = 0; i < 8; ++i) {
        int row = cRow * BM + tr * 8 + i;
        int gb = (row >> 10) * MODW;
        #pragma unroll
        for (int j4 = 0; j4 < 8; j4 += 4) {
            int col = cCol * BN + tc * 8 + j4;
            float vv[4];
            #pragma unroll
            for (int j = 0; j < 4; ++j) {
                float t = acc[i][j4 + j] + bias[col + j];
                if (EPI == 1) {
                    float u = t;
                    float inner = 0.7978845608028654f * (u + 0.044715f * u * u * u);
                    t = 0.5f * u * (1.f + tanhf(inner));
                } else if (EPI == 2) {
                    t = fmaf(gate[gb + col + j], t, res[(size_t)row * N + col + j]);
                }
                vv[j] = t;
            }
            *(float4*)(C + (size_t)row * N + col) =
                make_float4(vv[0], vv[1], vv[2], vv[3]);
        }
    }
}

// ---------------------------- launcher --------------------------------------
extern "C" void kernel_launch(void* const* d_in, const int* in_sizes, int n_in,
                              void* d_out, int out_size)
{
    const float* x      = (const float*)d_in[0];
    const float* c      = (const float*)d_in[1];
    const float* w_mod  = (const float*)d_in[2];
    const float* b_mod  = (const float*)d_in[3];
    const float* w_qkv  = (const float*)d_in[4];
    const float* b_qkv  = (const float*)d_in[5];
    const float* gq     = (const float*)d_in[6];
    const float* gk     = (const float*)d_in[7];
    const float* w_proj = (const float*)d_in[8];
    const float* b_proj = (const float*)d_in[9];
    const float* w1     = (const float*)d_in[10];
    const float* b1     = (const float*)d_in[11];
    const float* w2     = (const float*)d_in[12];
    const float* b2     = (const float*)d_in[13];
    float* out = (float*)d_out;

    float *p_mod, *p_xn, *p_qkv, *p_o, *p_x1, *p_h;
    cudaGetSymbolAddress((void**)&p_mod, g_mod);
    cudaGetSymbolAddress((void**)&p_xn,  g_xn);
    cudaGetSymbolAddress((void**)&p_qkv, g_qkv);
    cudaGetSymbolAddress((void**)&p_o,   g_o);
    cudaGetSymbolAddress((void**)&p_x1,  g_x1);
    cudaGetSymbolAddress((void**)&p_h,   g_h);

    cudaFuncSetAttribute(attn_kernel,
                         cudaFuncAttributeMaxDynamicSharedMemorySize, ATTN_SMEM);

    // 1. adaLN modulation
    mod_kernel<<<dim3(MODW / 128, Bsz), 128>>>(c, w_mod, b_mod, p_mod);
    // 2. LN + modulate (MSA): sh_msa @0, sc_msa @H
    ln_mod_kernel<<<ROWS, 256>>>(x, p_mod, 0, HID, p_xn);
    // 3. QKV GEMM
    sgemm_kernel<0><<<dim3(3 * HID / 128, ROWS / 128), 256>>>(
        p_xn, w_qkv, b_qkv, nullptr, nullptr, p_qkv, ROWS, 3 * HID, HID);
    // 4. per-head LN of q,k
    qkln_kernel<<<ROWS * 32 / 8, 256>>>(p_qkv, gq, gk);
    // 5. attention
    attn_kernel<<<dim3(SEQ / BQ, NH, Bsz), 256, ATTN_SMEM>>>(p_qkv, p_o);
    // 6. proj + gated residual: x1 = x + g_msa * (o @ w_proj + b_proj); g_msa @2H
    sgemm_kernel<2><<<dim3(HID / 128, ROWS / 128), 256>>>(
        p_o, w_proj, b_proj, x, p_mod + 2 * HID, p_x1, ROWS, HID, HID);
    // 7. LN + modulate (MLP): sh_mlp @3H, sc_mlp @4H
    ln_mod_kernel<<<ROWS, 256>>>(p_x1, p_mod, 3 * HID, 4 * HID, p_xn);
    // 8. MLP up + gelu
    sgemm_kernel<1><<<dim3(MLPD / 128, ROWS / 128), 256>>>(
        p_xn, w1, b1, nullptr, nullptr, p_h, ROWS, MLPD, HID);
    // 9. MLP down + gated residual: out = x1 + g_mlp * (h @ w2 + b2); g_mlp @5H
    sgemm_kernel<2><<<dim3(HID / 128, ROWS / 128), 256>>>(
        p_h, w2, b2, p_x1, p_mod + 5 * HID, out, ROWS, HID, MLPD);
}

// round 2
// speedup vs baseline: 2.0255x; 2.0255x over previous
#include <cuda_runtime.h>
#include <cuda_bf16.h>
#include <math.h>

// Problem constants
#define Bsz 16
#define SEQ 1024
#define HID 1152
#define NH 16
#define HD 72
#define MLPD 4608
#define ROWS (Bsz * SEQ)          // 16384
#define MODW (6 * HID)            // 6912
#define EPS 1e-6f

// ---------------- scratch (device globals; allocation-free) ----------------
__device__ float g_mod[Bsz * MODW];            // adaLN modulation (16 x 6912)
__device__ float g_xn [ROWS * HID];            // normalized/modulated input (reused)
__device__ float g_qkv[ROWS * 3 * HID];        // qkv projection (LN'd q,k in place)
__device__ float g_o  [ROWS * HID];            // attention output (B,N,H)
__device__ float g_x1 [ROWS * HID];            // x after attention residual
__device__ float g_h  [ROWS * MLPD];           // MLP hidden

__device__ __forceinline__ float to_tf32(float x) {
    float r;
    asm("cvt.rna.tf32.f32 %0, %1;" : "=f"(r) : "f"(x));
    return r;
}

// ---------------- kernel 1: mod = swish(c) @ w_mod + b_mod ----------------
__global__ __launch_bounds__(128) void mod_kernel(
    const float* __restrict__ c, const float* __restrict__ w_mod,
    const float* __restrict__ b_mod, float* __restrict__ mod)
{
    __shared__ float sc[HID];
    int b = blockIdx.y;
    for (int i = threadIdx.x; i < HID; i += blockDim.x) {
        float v = c[b * HID + i];
        sc[i] = v / (1.0f + expf(-v));
    }
    __syncthreads();
    int col = blockIdx.x * blockDim.x + threadIdx.x;   // 0..6911
    float acc = b_mod[col];
    #pragma unroll 4
    for (int k = 0; k < HID; ++k)
        acc = fmaf(sc[k], w_mod[(size_t)k * MODW + col], acc);
    mod[b * MODW + col] = acc;
}

// --------------- kernel 2: LN(x) * (1+sc) + sh  (per row) ------------------
__global__ __launch_bounds__(256) void ln_mod_kernel(
    const float* __restrict__ x, const float* __restrict__ mod,
    int shOff, int scOff, float* __restrict__ out)
{
    __shared__ float buf[HID];
    __shared__ float red[16];
    int row = blockIdx.x;
    int b = row >> 10;
    int tid = threadIdx.x;
    const float* xr = x + (size_t)row * HID;
    float s = 0.f, s2 = 0.f;
    for (int i = tid; i < HID; i += 256) {
        float v = xr[i];
        buf[i] = v;
        s += v; s2 += v * v;
    }
    #pragma unroll
    for (int o = 16; o; o >>= 1) {
        s  += __shfl_xor_sync(0xffffffffu, s,  o);
        s2 += __shfl_xor_sync(0xffffffffu, s2, o);
    }
    if ((tid & 31) == 0) { red[tid >> 5] = s; red[8 + (tid >> 5)] = s2; }
    __syncthreads();
    float S = 0.f, S2 = 0.f;
    #pragma unroll
    for (int w = 0; w < 8; ++w) { S += red[w]; S2 += red[8 + w]; }
    float mean = S * (1.f / HID);
    float var  = S2 * (1.f / HID) - mean * mean;
    float rstd = rsqrtf(var + EPS);
    const float* mrow = mod + b * MODW;
    float* orow = out + (size_t)row * HID;
    for (int i = tid; i < HID; i += 256) {
        float v = (buf[i] - mean) * rstd;
        orow[i] = fmaf(v, 1.f + mrow[scOff + i], mrow[shOff + i]);
    }
}

// --------------- kernel 3: per-head LN of q and k (in place) ---------------
__global__ __launch_bounds__(256) void qkln_kernel(
    float* __restrict__ qkv, const float* __restrict__ g_q,
    const float* __restrict__ g_k)
{
    int warp = blockIdx.x * 8 + (threadIdx.x >> 5);   // 0 .. 16384*32-1
    int lane = threadIdx.x & 31;
    int h  = warp & 15;
    int qk = (warp >> 4) & 1;
    int bn = warp >> 5;
    float* p = qkv + (size_t)bn * (3 * HID) + qk * HID + h * HD;
    float v0 = p[lane];
    float v1 = p[lane + 32];
    float v2 = (lane < 8) ? p[lane + 64] : 0.f;
    float s  = v0 + v1 + v2;
    float s2 = v0 * v0 + v1 * v1 + v2 * v2;
    #pragma unroll
    for (int o = 16; o; o >>= 1) {
        s  += __shfl_xor_sync(0xffffffffu, s,  o);
        s2 += __shfl_xor_sync(0xffffffffu, s2, o);
    }
    float mean = s * (1.f / HD);
    float var  = s2 * (1.f / HD) - mean * mean;
    float rstd = rsqrtf(var + EPS);
    const float* g = qk ? g_k : g_q;
    p[lane]      = (v0 - mean) * rstd * g[lane];
    p[lane + 32] = (v1 - mean) * rstd * g[lane + 32];
    if (lane < 8) p[lane + 64] = (v2 - mean) * rstd * g[lane + 64];
}

// --------------- kernel 4: flash attention (fp32) --------------------------
#define BQ 64
#define BKT 64
#define QSTR 81
#define PSTR 65
#define ATTN_SMEM ((3 * BQ * QSTR + BQ * PSTR) * 4)

__global__ __launch_bounds__(256) void attn_kernel(
    const float* __restrict__ qkv, float* __restrict__ o)
{
    extern __shared__ float sm[];
    float* qs = sm;                       // [64][81]
    float* ks = qs + BQ * QSTR;           // [64][81]
    float* vs = ks + BKT * QSTR;          // [64][81]
    float* P  = vs + BKT * QSTR;          // [64][65]

    int tid = threadIdx.x;
    int tr = tid >> 4, tc = tid & 15;
    int q0 = blockIdx.x * BQ;
    int h = blockIdx.y, b = blockIdx.z;
    const size_t baseBN = (size_t)b * SEQ * (3 * HID);
    const int hoff = h * HD;
    const float scale = 0.11785113019775793f;   // 1/sqrt(72)

    for (int idx = tid; idx < BQ * HD; idx += 256) {
        int r = idx / HD, d = idx - r * HD;
        qs[r * QSTR + d] = qkv[baseBN + (size_t)(q0 + r) * (3 * HID) + hoff + d];
    }
    for (int idx = tid; idx < BKT * 8; idx += 256)
        vs[(idx >> 3) * QSTR + 72 + (idx & 7)] = 0.f;

    float acc[4][5];
    #pragma unroll
    for (int i = 0; i < 4; ++i)
        #pragma unroll
        for (int j = 0; j < 5; ++j) acc[i][j] = 0.f;
    float mi[4] = {-INFINITY, -INFINITY, -INFINITY, -INFINITY};
    float li[4] = {0.f, 0.f, 0.f, 0.f};

    for (int kt = 0; kt < SEQ / BKT; ++kt) {
        __syncthreads();
        int k0 = kt * BKT;
        for (int idx = tid; idx < BKT * HD; idx += 256) {
            int r = idx / HD, d = idx - r * HD;
            size_t base = baseBN + (size_t)(k0 + r) * (3 * HID) + hoff + d;
            ks[r * QSTR + d] = qkv[base + HID];
            vs[r * QSTR + d] = qkv[base + 2 * HID];
        }
        __syncthreads();

        float sc[4][4];
        #pragma unroll
        for (int i = 0; i < 4; ++i)
            #pragma unroll
            for (int j = 0; j < 4; ++j) sc[i][j] = 0.f;
        for (int d = 0; d < HD; ++d) {
            float qa[4], kb[4];
            #pragma unroll
            for (int i = 0; i < 4; ++i) qa[i] = qs[(tr * 4 + i) * QSTR + d];
            #pragma unroll
            for (int j = 0; j < 4; ++j) kb[j] = ks[(tc * 4 + j) * QSTR + d];
            #pragma unroll
            for (int i = 0; i < 4; ++i)
                #pragma unroll
                for (int j = 0; j < 4; ++j)
                    sc[i][j] = fmaf(qa[i], kb[j], sc[i][j]);
        }
        #pragma unroll
        for (int i = 0; i < 4; ++i) {
            float s0 = sc[i][0] * scale, s1 = sc[i][1] * scale;
            float s2 = sc[i][2] * scale, s3 = sc[i][3] * scale;
            float rm = fmaxf(fmaxf(s0, s1), fmaxf(s2, s3));
            #pragma unroll
            for (int off = 8; off; off >>= 1)
                rm = fmaxf(rm, __shfl_xor_sync(0xffffffffu, rm, off));
            float newm = fmaxf(mi[i], rm);
            float p0 = __expf(s0 - newm), p1 = __expf(s1 - newm);
            float p2 = __expf(s2 - newm), p3 = __expf(s3 - newm);
            float ps = p0 + p1 + p2 + p3;
            #pragma unroll
            for (int off = 8; off; off >>= 1)
                ps += __shfl_xor_sync(0xffffffffu, ps, off);
            float alpha = __expf(mi[i] - newm);
            li[i] = li[i] * alpha + ps;
            mi[i] = newm;
            float* pr = P + (tr * 4 + i) * PSTR + tc * 4;
            pr[0] = p0; pr[1] = p1; pr[2] = p2; pr[3] = p3;
            #pragma unroll
            for (int j = 0; j < 5; ++j) acc[i][j] *= alpha;
        }
        __syncwarp();
        for (int kj = 0; kj < BKT; ++kj) {
            float vv[5];
            #pragma unroll
            for (int j = 0; j < 5; ++j) vv[j] = vs[kj * QSTR + tc * 5 + j];
            #pragma unroll
            for (int i = 0; i < 4; ++i) {
                float pp = P[(tr * 4 + i) * PSTR + kj];
                #pragma unroll
                for (int j = 0; j < 5; ++j)
                    acc[i][j] = fmaf(pp, vv[j], acc[i][j]);
            }
        }
    }
    #pragma unroll
    for (int i = 0; i < 4; ++i) {
        float inv = 1.f / li[i];
        int n = q0 + tr * 4 + i;
        size_t base = ((size_t)b * SEQ + n) * HID + hoff;
        #pragma unroll
        for (int j = 0; j < 5; ++j) {
            int d = tc * 5 + j;
            if (d < HD) o[base + d] = acc[i][j] * inv;
        }
    }
}

// --------------- kernel 5: TF32 tensor-core GEMM 128x128x16 ----------------
// 8 warps, each 64x32 (4x4 tiles of mma.m16n8k8).
// EPI 0: C = A@B + bias
// EPI 1: C = gelu_tanh(A@B + bias)
// EPI 2: C = res + gate[(row>>10)*MODW + col] * (A@B + bias)
#define TBM 128
#define TBN 128
#define TBK 16
#define ASTR 20     // As row stride (pad 16->20: conflict-free frag loads)
#define BSTR 132    // Bs row stride (pad 128->132)

__device__ __forceinline__ void mma_tf32(
    float& c0, float& c1, float& c2, float& c3,
    unsigned a0, unsigned a1, unsigned a2, unsigned a3,
    unsigned b0, unsigned b1)
{
    asm volatile(
        "mma.sync.aligned.m16n8k8.row.col.f32.tf32.tf32.f32 "
        "{%0,%1,%2,%3}, {%4,%5,%6,%7}, {%8,%9}, {%0,%1,%2,%3};"
        : "+f"(c0), "+f"(c1), "+f"(c2), "+f"(c3)
        : "r"(a0), "r"(a1), "r"(a2), "r"(a3), "r"(b0), "r"(b1));
}

template <int EPI>
__global__ __launch_bounds__(256) void tgemm_kernel(
    const float* __restrict__ A, const float* __restrict__ Bm,
    const float* __restrict__ bias, const float* __restrict__ res,
    const float* __restrict__ gate, float* __restrict__ C,
    int M, int N, int K)
{
    __shared__ float As[2][TBM][ASTR];
    __shared__ float Bs[2][TBK][BSTR];

    int tid = threadIdx.x;
    int lane = tid & 31;
    int warp = tid >> 5;
    int warpM = warp & 1;           // 2 warps in M
    int warpN = warp >> 1;          // 4 warps in N
    int m0 = warpM * 64;
    int n0 = warpN * 32;
    int grp = lane >> 2;            // 0..7
    int t4 = lane & 3;              // 0..3

    int cRow = blockIdx.y, cCol = blockIdx.x;
    const float* Ab = A + (size_t)cRow * TBM * K;
    const float* Bb = Bm + cCol * TBN;

    // global load assignments (2 float4 each for A and B)
    int aF0 = tid, aF1 = tid + 256;         // float4 index into 128x16 tile
    int bF0 = tid, bF1 = tid + 256;         // float4 index into 16x128 tile

    float acc[4][4][4];
    #pragma unroll
    for (int mi = 0; mi < 4; ++mi)
        #pragma unroll
        for (int ni = 0; ni < 4; ++ni)
            #pragma unroll
            for (int e = 0; e < 4; ++e) acc[mi][ni][e] = 0.f;

    // ---- load stage 0 ----
    float4 a40, a41, b40, b41;
    {
        int r0 = aF0 >> 2, c0i = (aF0 & 3) * 4;
        int r1 = aF1 >> 2, c1i = (aF1 & 3) * 4;
        a40 = *(const float4*)(Ab + (size_t)r0 * K + c0i);
        a41 = *(const float4*)(Ab + (size_t)r1 * K + c1i);
        int k0 = bF0 >> 5, n0i = (bF0 & 31) * 4;
        int k1 = bF1 >> 5, n1i = (bF1 & 31) * 4;
        b40 = *(const float4*)(Bb + (size_t)k0 * N + n0i);
        b41 = *(const float4*)(Bb + (size_t)k1 * N + n1i);
    }
    {
        int r0 = aF0 >> 2, c0i = (aF0 & 3) * 4;
        int r1 = aF1 >> 2, c1i = (aF1 & 3) * 4;
        *(float4*)&As[0][r0][c0i] = make_float4(to_tf32(a40.x), to_tf32(a40.y), to_tf32(a40.z), to_tf32(a40.w));
        *(float4*)&As[0][r1][c1i] = make_float4(to_tf32(a41.x), to_tf32(a41.y), to_tf32(a41.z), to_tf32(a41.w));
        int k0 = bF0 >> 5, n0i = (bF0 & 31) * 4;
        int k1 = bF1 >> 5, n1i = (bF1 & 31) * 4;
        *(float4*)&Bs[0][k0][n0i] = make_float4(to_tf32(b40.x), to_tf32(b40.y), to_tf32(b40.z), to_tf32(b40.w));
        *(float4*)&Bs[0][k1][n1i] = make_float4(to_tf32(b41.x), to_tf32(b41.y), to_tf32(b41.z), to_tf32(b41.w));
    }
    __syncthreads();

    int KT = K / TBK;
    for (int kt = 0; kt < KT; ++kt) {
        int cur = kt & 1;
        if (kt + 1 < KT) {
            const float* Abn = Ab + (kt + 1) * TBK;
            const float* Bbn = Bb + (size_t)(kt + 1) * TBK * N;
            int r0 = aF0 >> 2, c0i = (aF0 & 3) * 4;
            int r1 = aF1 >> 2, c1i = (aF1 & 3) * 4;
            a40 = *(const float4*)(Abn + (size_t)r0 * K + c0i);
            a41 = *(const float4*)(Abn + (size_t)r1 * K + c1i);
            int k0 = bF0 >> 5, n0i = (bF0 & 31) * 4;
            int k1 = bF1 >> 5, n1i = (bF1 & 31) * 4;
            b40 = *(const float4*)(Bbn + (size_t)k0 * N + n0i);
            b41 = *(const float4*)(Bbn + (size_t)k1 * N + n1i);
        }

        const float (*Asc)[ASTR] = As[cur];
        const float (*Bsc)[BSTR] = Bs[cur];
        #pragma unroll
        for (int ks = 0; ks < 2; ++ks) {
            int k8 = ks * 8;
            unsigned af[4][4], bf[4][2];
            #pragma unroll
            for (int mi = 0; mi < 4; ++mi) {
                int r = m0 + mi * 16 + grp;
                af[mi][0] = __float_as_uint(Asc[r][k8 + t4]);
                af[mi][1] = __float_as_uint(Asc[r + 8][k8 + t4]);
                af[mi][2] = __float_as_uint(Asc[r][k8 + t4 + 4]);
                af[mi][3] = __float_as_uint(Asc[r + 8][k8 + t4 + 4]);
            }
            #pragma unroll
            for (int ni = 0; ni < 4; ++ni) {
                int cc = n0 + ni * 8 + grp;
                bf[ni][0] = __float_as_uint(Bsc[k8 + t4][cc]);
                bf[ni][1] = __float_as_uint(Bsc[k8 + t4 + 4][cc]);
            }
            #pragma unroll
            for (int mi = 0; mi < 4; ++mi)
                #pragma unroll
                for (int ni = 0; ni < 4; ++ni)
                    mma_tf32(acc[mi][ni][0], acc[mi][ni][1], acc[mi][ni][2], acc[mi][ni][3],
                             af[mi][0], af[mi][1], af[mi][2], af[mi][3],
                             bf[ni][0], bf[ni][1]);
        }

        if (kt + 1 < KT) {
            int nxt = cur ^ 1;
            int r0 = aF0 >> 2, c0i = (aF0 & 3) * 4;
            int r1 = aF1 >> 2, c1i = (aF1 & 3) * 4;
            *(float4*)&As[nxt][r0][c0i] = make_float4(to_tf32(a40.x), to_tf32(a40.y), to_tf32(a40.z), to_tf32(a40.w));
            *(float4*)&As[nxt][r1][c1i] = make_float4(to_tf32(a41.x), to_tf32(a41.y), to_tf32(a41.z), to_tf32(a41.w));
            int k0 = bF0 >> 5, n0i = (bF0 & 31) * 4;
            int k1 = bF1 >> 5, n1i = (bF1 & 31) * 4;
            *(float4*)&Bs[nxt][k0][n0i] = make_float4(to_tf32(b40.x), to_tf32(b40.y), to_tf32(b40.z), to_tf32(b40.w));
            *(float4*)&Bs[nxt][k1][n1i] = make_float4(to_tf32(b41.x), to_tf32(b41.y), to_tf32(b41.z), to_tf32(b41.w));
        }
        __syncthreads();
    }

    // ---- epilogue ----
    #pragma unroll
    for (int mi = 0; mi < 4; ++mi) {
        #pragma unroll
        for (int half = 0; half < 2; ++half) {
            int row = cRow * TBM + m0 + mi * 16 + grp + half * 8;
            int gb = (row >> 10) * MODW;
            #pragma unroll
            for (int ni = 0; ni < 4; ++ni) {
                int col = cCol * TBN + n0 + ni * 8 + t4 * 2;
                float v0 = acc[mi][ni][half * 2 + 0] + bias[col];
                float v1 = acc[mi][ni][half * 2 + 1] + bias[col + 1];
                if (EPI == 1) {
                    float i0 = 0.7978845608028654f * (v0 + 0.044715f * v0 * v0 * v0);
                    float i1 = 0.7978845608028654f * (v1 + 0.044715f * v1 * v1 * v1);
                    v0 = 0.5f * v0 * (1.f + tanhf(i0));
                    v1 = 0.5f * v1 * (1.f + tanhf(i1));
                } else if (EPI == 2) {
                    v0 = fmaf(gate[gb + col],     v0, res[(size_t)row * N + col]);
                    v1 = fmaf(gate[gb + col + 1], v1, res[(size_t)row * N + col + 1]);
                }
                *(float2*)(C + (size_t)row * N + col) = make_float2(v0, v1);
            }
        }
    }
}

// ---------------------------- launcher --------------------------------------
extern "C" void kernel_launch(void* const* d_in, const int* in_sizes, int n_in,
                              void* d_out, int out_size)
{
    const float* x      = (const float*)d_in[0];
    const float* c      = (const float*)d_in[1];
    const float* w_mod  = (const float*)d_in[2];
    const float* b_mod  = (const float*)d_in[3];
    const float* w_qkv  = (const float*)d_in[4];
    const float* b_qkv  = (const float*)d_in[5];
    const float* gq     = (const float*)d_in[6];
    const float* gk     = (const float*)d_in[7];
    const float* w_proj = (const float*)d_in[8];
    const float* b_proj = (const float*)d_in[9];
    const float* w1     = (const float*)d_in[10];
    const float* b1     = (const float*)d_in[11];
    const float* w2     = (const float*)d_in[12];
    const float* b2     = (const float*)d_in[13];
    float* out = (float*)d_out;

    float *p_mod, *p_xn, *p_qkv, *p_o, *p_x1, *p_h;
    cudaGetSymbolAddress((void**)&p_mod, g_mod);
    cudaGetSymbolAddress((void**)&p_xn,  g_xn);
    cudaGetSymbolAddress((void**)&p_qkv, g_qkv);
    cudaGetSymbolAddress((void**)&p_o,   g_o);
    cudaGetSymbolAddress((void**)&p_x1,  g_x1);
    cudaGetSymbolAddress((void**)&p_h,   g_h);

    cudaFuncSetAttribute(attn_kernel,
                         cudaFuncAttributeMaxDynamicSharedMemorySize, ATTN_SMEM);

    // 1. adaLN modulation
    mod_kernel<<<dim3(MODW / 128, Bsz), 128>>>(c, w_mod, b_mod, p_mod);
    // 2. LN + modulate (MSA)
    ln_mod_kernel<<<ROWS, 256>>>(x, p_mod, 0, HID, p_xn);
    // 3. QKV GEMM (tf32 tensor)
    tgemm_kernel<0><<<dim3(3 * HID / TBN, ROWS / TBM), 256>>>(
        p_xn, w_qkv, b_qkv, nullptr, nullptr, p_qkv, ROWS, 3 * HID, HID);
    // 4. per-head LN of q,k
    qkln_kernel<<<ROWS * 32 / 8, 256>>>(p_qkv, gq, gk);
    // 5. attention
    attn_kernel<<<dim3(SEQ / BQ, NH, Bsz), 256, ATTN_SMEM>>>(p_qkv, p_o);
    // 6. proj + gated residual
    tgemm_kernel<2><<<dim3(HID / TBN, ROWS / TBM), 256>>>(
        p_o, w_proj, b_proj, x, p_mod + 2 * HID, p_x1, ROWS, HID, HID);
    // 7. LN + modulate (MLP)
    ln_mod_kernel<<<ROWS, 256>>>(p_x1, p_mod, 3 * HID, 4 * HID, p_xn);
    // 8. MLP up + gelu
    tgemm_kernel<1><<<dim3(MLPD / TBN, ROWS / TBM), 256>>>(
        p_xn, w1, b1, nullptr, nullptr, p_h, ROWS, MLPD, HID);
    // 9. MLP down + gated residual
    tgemm_kernel<2><<<dim3(HID / TBN, ROWS / TBM), 256>>>(
        p_h, w2, b2, p_x1, p_mod + 5 * HID, out, ROWS, HID, MLPD);
}

// round 3
// speedup vs baseline: 3.3291x; 1.6436x over previous
#include <cuda_runtime.h>
#include <cuda_bf16.h>
#include <math.h>

// Problem constants
#define Bsz 16
#define SEQ 1024
#define HID 1152
#define NH 16
#define HD 72
#define MLPD 4608
#define ROWS (Bsz * SEQ)          // 16384
#define MODW (6 * HID)            // 6912
#define EPS 1e-6f

// ---------------- scratch (device globals; allocation-free) ----------------
__device__ float g_mod[Bsz * MODW];
__device__ float g_xn [ROWS * HID];
__device__ float g_qkv[ROWS * 3 * HID];
__device__ float g_o  [ROWS * HID];
__device__ float g_x1 [ROWS * HID];
__device__ float g_h  [ROWS * MLPD];

__device__ __forceinline__ float to_tf32(float x) {
    float r;
    asm("cvt.rna.tf32.f32 %0, %1;" : "=f"(r) : "f"(x));
    return r;
}

__device__ __forceinline__ void mma_tf32(
    float& c0, float& c1, float& c2, float& c3,
    unsigned a0, unsigned a1, unsigned a2, unsigned a3,
    unsigned b0, unsigned b1)
{
    asm volatile(
        "mma.sync.aligned.m16n8k8.row.col.f32.tf32.tf32.f32 "
        "{%0,%1,%2,%3}, {%4,%5,%6,%7}, {%8,%9}, {%0,%1,%2,%3};"
        : "+f"(c0), "+f"(c1), "+f"(c2), "+f"(c3)
        : "r"(a0), "r"(a1), "r"(a2), "r"(a3), "r"(b0), "r"(b1));
}

__device__ __forceinline__ void cp16(float* dst, const float* src) {
    unsigned d = (unsigned)__cvta_generic_to_shared(dst);
    asm volatile("cp.async.cg.shared.global [%0], [%1], 16;" :: "r"(d), "l"(src));
}
__device__ __forceinline__ void cp_commit() {
    asm volatile("cp.async.commit_group;");
}
template <int N> __device__ __forceinline__ void cp_wait() {
    asm volatile("cp.async.wait_group %0;" :: "n"(N));
}

// ---------------- kernel 1: mod = swish(c) @ w_mod + b_mod ----------------
__global__ __launch_bounds__(128) void mod_kernel(
    const float* __restrict__ c, const float* __restrict__ w_mod,
    const float* __restrict__ b_mod, float* __restrict__ mod)
{
    __shared__ float sc[HID];
    int b = blockIdx.y;
    for (int i = threadIdx.x; i < HID; i += blockDim.x) {
        float v = c[b * HID + i];
        sc[i] = v / (1.0f + expf(-v));
    }
    __syncthreads();
    int col = blockIdx.x * blockDim.x + threadIdx.x;
    float acc = b_mod[col];
    #pragma unroll 4
    for (int k = 0; k < HID; ++k)
        acc = fmaf(sc[k], w_mod[(size_t)k * MODW + col], acc);
    mod[b * MODW + col] = acc;
}

// --------------- kernel 2: LN(x) * (1+sc) + sh  (per row) ------------------
__global__ __launch_bounds__(256) void ln_mod_kernel(
    const float* __restrict__ x, const float* __restrict__ mod,
    int shOff, int scOff, float* __restrict__ out)
{
    __shared__ float buf[HID];
    __shared__ float red[16];
    int row = blockIdx.x;
    int b = row >> 10;
    int tid = threadIdx.x;
    const float* xr = x + (size_t)row * HID;
    float s = 0.f, s2 = 0.f;
    for (int i = tid; i < HID; i += 256) {
        float v = xr[i];
        buf[i] = v;
        s += v; s2 += v * v;
    }
    #pragma unroll
    for (int o = 16; o; o >>= 1) {
        s  += __shfl_xor_sync(0xffffffffu, s,  o);
        s2 += __shfl_xor_sync(0xffffffffu, s2, o);
    }
    if ((tid & 31) == 0) { red[tid >> 5] = s; red[8 + (tid >> 5)] = s2; }
    __syncthreads();
    float S = 0.f, S2 = 0.f;
    #pragma unroll
    for (int w = 0; w < 8; ++w) { S += red[w]; S2 += red[8 + w]; }
    float mean = S * (1.f / HID);
    float var  = S2 * (1.f / HID) - mean * mean;
    float rstd = rsqrtf(var + EPS);
    const float* mrow = mod + b * MODW;
    float* orow = out + (size_t)row * HID;
    for (int i = tid; i < HID; i += 256) {
        float v = (buf[i] - mean) * rstd;
        orow[i] = fmaf(v, 1.f + mrow[scOff + i], mrow[shOff + i]);
    }
}

// --------------- kernel 3: per-head LN of q and k (in place) ---------------
__global__ __launch_bounds__(256) void qkln_kernel(
    float* __restrict__ qkv, const float* __restrict__ g_q,
    const float* __restrict__ g_k)
{
    int warp = blockIdx.x * 8 + (threadIdx.x >> 5);
    int lane = threadIdx.x & 31;
    int h  = warp & 15;
    int qk = (warp >> 4) & 1;
    int bn = warp >> 5;
    float* p = qkv + (size_t)bn * (3 * HID) + qk * HID + h * HD;
    float v0 = p[lane];
    float v1 = p[lane + 32];
    float v2 = (lane < 8) ? p[lane + 64] : 0.f;
    float s  = v0 + v1 + v2;
    float s2 = v0 * v0 + v1 * v1 + v2 * v2;
    #pragma unroll
    for (int o = 16; o; o >>= 1) {
        s  += __shfl_xor_sync(0xffffffffu, s,  o);
        s2 += __shfl_xor_sync(0xffffffffu, s2, o);
    }
    float mean = s * (1.f / HD);
    float var  = s2 * (1.f / HD) - mean * mean;
    float rstd = rsqrtf(var + EPS);
    const float* g = qk ? g_k : g_q;
    p[lane]      = (v0 - mean) * rstd * g[lane];
    p[lane + 32] = (v1 - mean) * rstd * g[lane + 32];
    if (lane < 8) p[lane + 64] = (v2 - mean) * rstd * g[lane + 64];
}

// --------------- kernel 4: flash attention (tf32 tensor cores) --------------
// BQ=128, BK=64, 256 threads = 8 warps; warp w owns queries [w*16, w*16+16)
// and the FULL 64-key score stripe -> all softmax reductions are intra-quad.
#define AQ 128
#define AK 64
#define QST 76      // stride for qs/ks/vs (conflict-free frag loads)
#define PST 68      // stride for ps
#define ATTN_SMEM ((AQ * QST + 2 * AK * QST + AQ * PST) * 4)

__global__ __launch_bounds__(256) void attn_kernel(
    const float* __restrict__ qkv, float* __restrict__ o)
{
    extern __shared__ float sm[];
    float* qs = sm;                    // [128][76]
    float* ks = qs + AQ * QST;         // [64][76]
    float* vs = ks + AK * QST;         // [64][76]
    float* ps = vs + AK * QST;         // [128][68]

    int tid = threadIdx.x;
    int lane = tid & 31;
    int warp = tid >> 5;
    int grp = lane >> 2;       // 0..7
    int t4 = lane & 3;         // 0..3
    int m0 = warp * 16;

    int q0 = blockIdx.x * AQ;
    int h = blockIdx.y, b = blockIdx.z;
    const size_t baseBN = (size_t)b * SEQ * (3 * HID);
    const int hoff = h * HD;
    const float scale = 0.11785113019775793f;   // 1/sqrt(72)

    // load Q tile (float4, HD=72 -> 18 chunks/row)
    for (int idx = tid; idx < AQ * 18; idx += 256) {
        int r = idx / 18, d4 = (idx - r * 18) * 4;
        float4 v = *(const float4*)(qkv + baseBN + (size_t)(q0 + r) * (3 * HID) + hoff + d4);
        *(float4*)(qs + r * QST + d4) = v;
    }

    float accO[9][4];
    #pragma unroll
    for (int di = 0; di < 9; ++di)
        #pragma unroll
        for (int e = 0; e < 4; ++e) accO[di][e] = 0.f;
    float mi0 = -INFINITY, mi1 = -INFINITY;
    float li0 = 0.f, li1 = 0.f;

    for (int kt = 0; kt < SEQ / AK; ++kt) {
        __syncthreads();   // prior iter done with ks/vs (and qs ready 1st iter)
        int k0 = kt * AK;
        for (int idx = tid; idx < AK * 18; idx += 256) {
            int r = idx / 18, d4 = (idx - r * 18) * 4;
            size_t base = baseBN + (size_t)(k0 + r) * (3 * HID) + hoff + d4;
            *(float4*)(ks + r * QST + d4) = *(const float4*)(qkv + base + HID);
            *(float4*)(vs + r * QST + d4) = *(const float4*)(qkv + base + 2 * HID);
        }
        __syncthreads();

        // ---- S = Q K^T : warp stripe m16 x 64, k = 72 (9 k8-steps) ----
        float sacc[8][4];
        #pragma unroll
        for (int ni = 0; ni < 8; ++ni)
            #pragma unroll
            for (int e = 0; e < 4; ++e) sacc[ni][e] = 0.f;
        #pragma unroll
        for (int k8 = 0; k8 < 72; k8 += 8) {
            unsigned a0 = __float_as_uint(qs[(m0 + grp) * QST + k8 + t4]);
            unsigned a1 = __float_as_uint(qs[(m0 + grp + 8) * QST + k8 + t4]);
            unsigned a2 = __float_as_uint(qs[(m0 + grp) * QST + k8 + t4 + 4]);
            unsigned a3 = __float_as_uint(qs[(m0 + grp + 8) * QST + k8 + t4 + 4]);
            #pragma unroll
            for (int ni = 0; ni < 8; ++ni) {
                unsigned b0 = __float_as_uint(ks[(ni * 8 + grp) * QST + k8 + t4]);
                unsigned b1 = __float_as_uint(ks[(ni * 8 + grp) * QST + k8 + t4 + 4]);
                mma_tf32(sacc[ni][0], sacc[ni][1], sacc[ni][2], sacc[ni][3],
                         a0, a1, a2, a3, b0, b1);
            }
        }

        // ---- online softmax (rows grp, grp+8; cols across ni,t4) ----
        float rmax0 = -INFINITY, rmax1 = -INFINITY;
        #pragma unroll
        for (int ni = 0; ni < 8; ++ni) {
            sacc[ni][0] *= scale; sacc[ni][1] *= scale;
            sacc[ni][2] *= scale; sacc[ni][3] *= scale;
            rmax0 = fmaxf(rmax0, fmaxf(sacc[ni][0], sacc[ni][1]));
            rmax1 = fmaxf(rmax1, fmaxf(sacc[ni][2], sacc[ni][3]));
        }
        #pragma unroll
        for (int off = 1; off < 4; off <<= 1) {
            rmax0 = fmaxf(rmax0, __shfl_xor_sync(0xffffffffu, rmax0, off));
            rmax1 = fmaxf(rmax1, __shfl_xor_sync(0xffffffffu, rmax1, off));
        }
        float newm0 = fmaxf(mi0, rmax0);
        float newm1 = fmaxf(mi1, rmax1);
        float alpha0 = __expf(mi0 - newm0);
        float alpha1 = __expf(mi1 - newm1);
        mi0 = newm0; mi1 = newm1;
        float rsum0 = 0.f, rsum1 = 0.f;
        #pragma unroll
        for (int ni = 0; ni < 8; ++ni) {
            float p0 = to_tf32(__expf(sacc[ni][0] - newm0));
            float p1 = to_tf32(__expf(sacc[ni][1] - newm0));
            float p2 = to_tf32(__expf(sacc[ni][2] - newm1));
            float p3 = to_tf32(__expf(sacc[ni][3] - newm1));
            rsum0 += p0 + p1; rsum1 += p2 + p3;
            *(float2*)(ps + (m0 + grp) * PST + ni * 8 + t4 * 2) = make_float2(p0, p1);
            *(float2*)(ps + (m0 + grp + 8) * PST + ni * 8 + t4 * 2) = make_float2(p2, p3);
        }
        #pragma unroll
        for (int off = 1; off < 4; off <<= 1) {
            rsum0 += __shfl_xor_sync(0xffffffffu, rsum0, off);
            rsum1 += __shfl_xor_sync(0xffffffffu, rsum1, off);
        }
        li0 = li0 * alpha0 + rsum0;
        li1 = li1 * alpha1 + rsum1;
        #pragma unroll
        for (int di = 0; di < 9; ++di) {
            accO[di][0] *= alpha0; accO[di][1] *= alpha0;
            accO[di][2] *= alpha1; accO[di][3] *= alpha1;
        }
        __syncwarp();   // ps stripe is warp-private: warp-level sync suffices

        // ---- O += P V : A = P (m16 x k64), B = V (k64 x 72) ----
        #pragma unroll
        for (int k8 = 0; k8 < 64; k8 += 8) {
            unsigned a0 = __float_as_uint(ps[(m0 + grp) * PST + k8 + t4]);
            unsigned a1 = __float_as_uint(ps[(m0 + grp + 8) * PST + k8 + t4]);
            unsigned a2 = __float_as_uint(ps[(m0 + grp) * PST + k8 + t4 + 4]);
            unsigned a3 = __float_as_uint(ps[(m0 + grp + 8) * PST + k8 + t4 + 4]);
            #pragma unroll
            for (int di = 0; di < 9; ++di) {
                unsigned b0 = __float_as_uint(vs[(k8 + t4) * QST + di * 8 + grp]);
                unsigned b1 = __float_as_uint(vs[(k8 + t4 + 4) * QST + di * 8 + grp]);
                mma_tf32(accO[di][0], accO[di][1], accO[di][2], accO[di][3],
                         a0, a1, a2, a3, b0, b1);
            }
        }
        __syncwarp();   // done reading ps before next iter rewrites it
    }

    // ---- write O / li ----
    float inv0 = 1.f / li0, inv1 = 1.f / li1;
    int row0 = q0 + m0 + grp;
    size_t b0a = ((size_t)b * SEQ + row0) * HID + hoff;
    size_t b1a = ((size_t)b * SEQ + row0 + 8) * HID + hoff;
    #pragma unroll
    for (int di = 0; di < 9; ++di) {
        int d = di * 8 + t4 * 2;
        *(float2*)(o + b0a + d) = make_float2(accO[di][0] * inv0, accO[di][1] * inv0);
        *(float2*)(o + b1a + d) = make_float2(accO[di][2] * inv1, accO[di][3] * inv1);
    }
}

// --------------- kernel 5: TF32 GEMM, cp.async 3-stage pipeline -------------
// 128x128x16 tile, 8 warps each 64x32 (4x4 m16n8k8 tiles).
// EPI 0: C = A@B + bias;  1: gelu;  2: res + gate * (A@B + bias)
#define TBM 128
#define TBN 128
#define TBK 16
#define ASTR 20
#define BSTR 136
#define NSTAGE 3
#define GEMM_SMEM (NSTAGE * (TBM * ASTR + TBK * BSTR) * 4)

template <int EPI>
__global__ __launch_bounds__(256) void tgemm_kernel(
    const float* __restrict__ A, const float* __restrict__ Bm,
    const float* __restrict__ bias, const float* __restrict__ res,
    const float* __restrict__ gate, float* __restrict__ C,
    int M, int N, int K)
{
    extern __shared__ float smem[];
    float* As = smem;                          // [NSTAGE][TBM][ASTR]
    float* Bs = smem + NSTAGE * TBM * ASTR;    // [NSTAGE][TBK][BSTR]

    int tid = threadIdx.x;
    int lane = tid & 31;
    int warp = tid >> 5;
    int m0 = (warp & 1) * 64;
    int n0 = (warp >> 1) * 32;
    int grp = lane >> 2;
    int t4 = lane & 3;

    int cRow = blockIdx.y, cCol = blockIdx.x;
    const float* Ab = A + (size_t)cRow * TBM * K;
    const float* Bb = Bm + cCol * TBN;

    // per-thread load slots: A tile = 512 f4 chunks, B tile = 512 f4 chunks
    int ar0 = tid >> 2,          ac0 = (tid & 3) * 4;
    int ar1 = (tid + 256) >> 2,  ac1 = ac0;
    int bk0 = tid >> 5,          bn0 = (tid & 31) * 4;
    int bk1 = bk0 + 8,           bn1 = bn0;

    float acc[4][4][4];
    #pragma unroll
    for (int mi = 0; mi < 4; ++mi)
        #pragma unroll
        for (int ni = 0; ni < 4; ++ni)
            #pragma unroll
            for (int e = 0; e < 4; ++e) acc[mi][ni][e] = 0.f;

    int KT = K / TBK;

    // prologue: stages 0..NSTAGE-2
    #pragma unroll
    for (int s = 0; s < NSTAGE - 1; ++s) {
        float* Ad = As + s * TBM * ASTR;
        float* Bd = Bs + s * TBK * BSTR;
        const float* Asrc = Ab + s * TBK;
        const float* Bsrc = Bb + (size_t)s * TBK * N;
        cp16(Ad + ar0 * ASTR + ac0, Asrc + (size_t)ar0 * K + ac0);
        cp16(Ad + ar1 * ASTR + ac1, Asrc + (size_t)ar1 * K + ac1);
        cp16(Bd + bk0 * BSTR + bn0, Bsrc + (size_t)bk0 * N + bn0);
        cp16(Bd + bk1 * BSTR + bn1, Bsrc + (size_t)bk1 * N + bn1);
        cp_commit();
    }

    for (int kt = 0; kt < KT; ++kt) {
        cp_wait<NSTAGE - 2>();
        __syncthreads();   // stage kt ready; all warps past compute of kt-1

        int pf = kt + NSTAGE - 1;
        if (pf < KT) {
            int s = pf % NSTAGE;
            float* Ad = As + s * TBM * ASTR;
            float* Bd = Bs + s * TBK * BSTR;
            const float* Asrc = Ab + pf * TBK;
            const float* Bsrc = Bb + (size_t)pf * TBK * N;
            cp16(Ad + ar0 * ASTR + ac0, Asrc + (size_t)ar0 * K + ac0);
            cp16(Ad + ar1 * ASTR + ac1, Asrc + (size_t)ar1 * K + ac1);
            cp16(Bd + bk0 * BSTR + bn0, Bsrc + (size_t)bk0 * N + bn0);
            cp16(Bd + bk1 * BSTR + bn1, Bsrc + (size_t)bk1 * N + bn1);
        }
        cp_commit();

        const float* Asc = As + (kt % NSTAGE) * TBM * ASTR;
        const float* Bsc = Bs + (kt % NSTAGE) * TBK * BSTR;
        #pragma unroll
        for (int ks = 0; ks < 2; ++ks) {
            int k8 = ks * 8;
            unsigned af[4][4], bf[4][2];
            #pragma unroll
            for (int mi = 0; mi < 4; ++mi) {
                int r = m0 + mi * 16 + grp;
                af[mi][0] = __float_as_uint(Asc[r * ASTR + k8 + t4]);
                af[mi][1] = __float_as_uint(Asc[(r + 8) * ASTR + k8 + t4]);
                af[mi][2] = __float_as_uint(Asc[r * ASTR + k8 + t4 + 4]);
                af[mi][3] = __float_as_uint(Asc[(r + 8) * ASTR + k8 + t4 + 4]);
            }
            #pragma unroll
            for (int ni = 0; ni < 4; ++ni) {
                int cc = n0 + ni * 8 + grp;
                bf[ni][0] = __float_as_uint(Bsc[(k8 + t4) * BSTR + cc]);
                bf[ni][1] = __float_as_uint(Bsc[(k8 + t4 + 4) * BSTR + cc]);
            }
            #pragma unroll
            for (int mi = 0; mi < 4; ++mi)
                #pragma unroll
                for (int ni = 0; ni < 4; ++ni)
                    mma_tf32(acc[mi][ni][0], acc[mi][ni][1], acc[mi][ni][2], acc[mi][ni][3],
                             af[mi][0], af[mi][1], af[mi][2], af[mi][3],
                             bf[ni][0], bf[ni][1]);
        }
    }

    // ---- epilogue ----
    #pragma unroll
    for (int mi = 0; mi < 4; ++mi) {
        #pragma unroll
        for (int half = 0; half < 2; ++half) {
            int row = cRow * TBM + m0 + mi * 16 + grp + half * 8;
            int gb = (row >> 10) * MODW;
            #pragma unroll
            for (int ni = 0; ni < 4; ++ni) {
                int col = cCol * TBN + n0 + ni * 8 + t4 * 2;
                float v0 = acc[mi][ni][half * 2 + 0] + bias[col];
                float v1 = acc[mi][ni][half * 2 + 1] + bias[col + 1];
                if (EPI == 1) {
                    // gelu(v) = v * 0.5*(1+tanh(i)) = v / (1 + exp(-2i))
                    float i0 = 0.7978845608028654f * (v0 + 0.044715f * v0 * v0 * v0);
                    float i1 = 0.7978845608028654f * (v1 + 0.044715f * v1 * v1 * v1);
                    v0 = v0 / (1.f + __expf(-2.f * i0));
                    v1 = v1 / (1.f + __expf(-2.f * i1));
                } else if (EPI == 2) {
                    v0 = fmaf(gate[gb + col],     v0, res[(size_t)row * N + col]);
                    v1 = fmaf(gate[gb + col + 1], v1, res[(size_t)row * N + col + 1]);
                }
                *(float2*)(C + (size_t)row * N + col) = make_float2(v0, v1);
            }
        }
    }
}

// ---------------------------- launcher --------------------------------------
extern "C" void kernel_launch(void* const* d_in, const int* in_sizes, int n_in,
                              void* d_out, int out_size)
{
    const float* x      = (const float*)d_in[0];
    const float* c      = (const float*)d_in[1];
    const float* w_mod  = (const float*)d_in[2];
    const float* b_mod  = (const float*)d_in[3];
    const float* w_qkv  = (const float*)d_in[4];
    const float* b_qkv  = (const float*)d_in[5];
    const float* gq     = (const float*)d_in[6];
    const float* gk     = (const float*)d_in[7];
    const float* w_proj = (const float*)d_in[8];
    const float* b_proj = (const float*)d_in[9];
    const float* w1     = (const float*)d_in[10];
    const float* b1     = (const float*)d_in[11];
    const float* w2     = (const float*)d_in[12];
    const float* b2     = (const float*)d_in[13];
    float* out = (float*)d_out;

    float *p_mod, *p_xn, *p_qkv, *p_o, *p_x1, *p_h;
    cudaGetSymbolAddress((void**)&p_mod, g_mod);
    cudaGetSymbolAddress((void**)&p_xn,  g_xn);
    cudaGetSymbolAddress((void**)&p_qkv, g_qkv);
    cudaGetSymbolAddress((void**)&p_o,   g_o);
    cudaGetSymbolAddress((void**)&p_x1,  g_x1);
    cudaGetSymbolAddress((void**)&p_h,   g_h);

    cudaFuncSetAttribute(attn_kernel,
                         cudaFuncAttributeMaxDynamicSharedMemorySize, ATTN_SMEM);
    cudaFuncSetAttribute(tgemm_kernel<0>,
                         cudaFuncAttributeMaxDynamicSharedMemorySize, GEMM_SMEM);
    cudaFuncSetAttribute(tgemm_kernel<1>,
                         cudaFuncAttributeMaxDynamicSharedMemorySize, GEMM_SMEM);
    cudaFuncSetAttribute(tgemm_kernel<2>,
                         cudaFuncAttributeMaxDynamicSharedMemorySize, GEMM_SMEM);

    // 1. adaLN modulation
    mod_kernel<<<dim3(MODW / 128, Bsz), 128>>>(c, w_mod, b_mod, p_mod);
    // 2. LN + modulate (MSA)
    ln_mod_kernel<<<ROWS, 256>>>(x, p_mod, 0, HID, p_xn);
    // 3. QKV GEMM
    tgemm_kernel<0><<<dim3(3 * HID / TBN, ROWS / TBM), 256, GEMM_SMEM>>>(
        p_xn, w_qkv, b_qkv, nullptr, nullptr, p_qkv, ROWS, 3 * HID, HID);
    // 4. per-head LN of q,k
    qkln_kernel<<<ROWS * 32 / 8, 256>>>(p_qkv, gq, gk);
    // 5. attention (tf32 tensor cores)
    attn_kernel<<<dim3(SEQ / AQ, NH, Bsz), 256, ATTN_SMEM>>>(p_qkv, p_o);
    // 6. proj + gated residual
    tgemm_kernel<2><<<dim3(HID / TBN, ROWS / TBM), 256, GEMM_SMEM>>>(
        p_o, w_proj, b_proj, x, p_mod + 2 * HID, p_x1, ROWS, HID, HID);
    // 7. LN + modulate (MLP)
    ln_mod_kernel<<<ROWS, 256>>>(p_x1, p_mod, 3 * HID, 4 * HID, p_xn);
    // 8. MLP up + gelu
    tgemm_kernel<1><<<dim3(MLPD / TBN, ROWS / TBM), 256, GEMM_SMEM>>>(
        p_xn, w1, b1, nullptr, nullptr, p_h, ROWS, MLPD, HID);
    // 9. MLP down + gated residual
    tgemm_kernel<2><<<dim3(HID / TBN, ROWS / TBM), 256, GEMM_SMEM>>>(
        p_h, w2, b2, p_x1, p_mod + 5 * HID, out, ROWS, HID, MLPD);
}

// round 5
// speedup vs baseline: 4.7490x; 1.4265x over previous
#include <cuda_runtime.h>
#include <cuda_fp16.h>
#include <math.h>
#include <stdint.h>

// Problem constants
#define Bsz 16
#define SEQ 1024
#define HID 1152
#define NH 16
#define HD 72
#define MLPD 4608
#define ROWS (Bsz * SEQ)          // 16384
#define MODW (6 * HID)            // 6912
#define EPS 1e-6f

// ---------------- scratch (device globals; allocation-free) ----------------
__device__ float  g_mod[Bsz * MODW];
__device__ __half g_xn16[ROWS * HID];
__device__ float  g_qkv[ROWS * 3 * HID];
__device__ __half g_o16[ROWS * HID];
__device__ float  g_x1[ROWS * HID];
__device__ __half g_h16[ROWS * MLPD];
// fp16 transposed weights [N][K]
__device__ __half g_wqkvT16[3 * HID * HID];
__device__ __half g_wprojT16[HID * HID];
__device__ __half g_w1T16[HID * MLPD];
__device__ __half g_w2T16[MLPD * HID];

__device__ __forceinline__ float to_tf32(float x) {
    float r;
    asm("cvt.rna.tf32.f32 %0, %1;" : "=f"(r) : "f"(x));
    return r;
}

__device__ __forceinline__ void mma_tf32(
    float& c0, float& c1, float& c2, float& c3,
    unsigned a0, unsigned a1, unsigned a2, unsigned a3,
    unsigned b0, unsigned b1)
{
    asm volatile(
        "mma.sync.aligned.m16n8k8.row.col.f32.tf32.tf32.f32 "
        "{%0,%1,%2,%3}, {%4,%5,%6,%7}, {%8,%9}, {%0,%1,%2,%3};"
        : "+f"(c0), "+f"(c1), "+f"(c2), "+f"(c3)
        : "r"(a0), "r"(a1), "r"(a2), "r"(a3), "r"(b0), "r"(b1));
}

__device__ __forceinline__ void mma_f16(
    float& c0, float& c1, float& c2, float& c3,
    unsigned a0, unsigned a1, unsigned a2, unsigned a3,
    unsigned b0, unsigned b1)
{
    asm volatile(
        "mma.sync.aligned.m16n8k16.row.col.f32.f16.f16.f32 "
        "{%0,%1,%2,%3}, {%4,%5,%6,%7}, {%8,%9}, {%0,%1,%2,%3};"
        : "+f"(c0), "+f"(c1), "+f"(c2), "+f"(c3)
        : "r"(a0), "r"(a1), "r"(a2), "r"(a3), "r"(b0), "r"(b1));
}

__device__ __forceinline__ void cp16s(uint32_t dst, const void* src) {
    asm volatile("cp.async.cg.shared.global [%0], [%1], 16;" :: "r"(dst), "l"(src));
}
__device__ __forceinline__ void cp_commit() {
    asm volatile("cp.async.commit_group;");
}
template <int N> __device__ __forceinline__ void cp_wait() {
    asm volatile("cp.async.wait_group %0;" :: "n"(N));
}
__device__ __forceinline__ uint32_t smem_u32(const void* p) {
    uint32_t a;
    asm("{ .reg .u64 t; cvta.to.shared.u64 t, %1; cvt.u32.u64 %0, t; }"
        : "=r"(a) : "l"(p));
    return a;
}

// ------- kernel 0: weight convert+transpose fp32 [K][N] -> fp16 [N][K] ------
__global__ __launch_bounds__(256) void wcvt_kernel(
    const float* __restrict__ w, __half* __restrict__ wt, int K, int N)
{
    __shared__ float t[32][33];
    int n0 = blockIdx.x * 32, k0 = blockIdx.y * 32;
    int tx = threadIdx.x & 31, ty = threadIdx.x >> 5;   // 32x8
    #pragma unroll
    for (int j = 0; j < 32; j += 8)
        t[ty + j][tx] = w[(size_t)(k0 + ty + j) * N + n0 + tx];
    __syncthreads();
    #pragma unroll
    for (int j = 0; j < 32; j += 8)
        wt[(size_t)(n0 + ty + j) * K + k0 + tx] = __float2half(t[tx][ty + j]);
}

// ---------------- kernel 1: mod = swish(c) @ w_mod + b_mod ----------------
__global__ __launch_bounds__(128) void mod_kernel(
    const float* __restrict__ c, const float* __restrict__ w_mod,
    const float* __restrict__ b_mod, float* __restrict__ mod)
{
    __shared__ float sc[HID];
    int b = blockIdx.y;
    for (int i = threadIdx.x; i < HID; i += blockDim.x) {
        float v = c[b * HID + i];
        sc[i] = v / (1.0f + expf(-v));
    }
    __syncthreads();
    int col = blockIdx.x * blockDim.x + threadIdx.x;
    float acc = b_mod[col];
    #pragma unroll 4
    for (int k = 0; k < HID; ++k)
        acc = fmaf(sc[k], w_mod[(size_t)k * MODW + col], acc);
    mod[b * MODW + col] = acc;
}

// --------- kernel 2: LN(x) * (1+sc) + sh  (per row), fp16 output ------------
__global__ __launch_bounds__(256) void ln_mod_kernel(
    const float* __restrict__ x, const float* __restrict__ mod,
    int shOff, int scOff, __half* __restrict__ out)
{
    __shared__ float buf[HID];
    __shared__ float red[16];
    int row = blockIdx.x;
    int b = row >> 10;
    int tid = threadIdx.x;
    const float* xr = x + (size_t)row * HID;
    float s = 0.f, s2 = 0.f;
    for (int i = tid; i < HID; i += 256) {
        float v = xr[i];
        buf[i] = v;
        s += v; s2 += v * v;
    }
    #pragma unroll
    for (int o = 16; o; o >>= 1) {
        s  += __shfl_xor_sync(0xffffffffu, s,  o);
        s2 += __shfl_xor_sync(0xffffffffu, s2, o);
    }
    if ((tid & 31) == 0) { red[tid >> 5] = s; red[8 + (tid >> 5)] = s2; }
    __syncthreads();
    float S = 0.f, S2 = 0.f;
    #pragma unroll
    for (int w = 0; w < 8; ++w) { S += red[w]; S2 += red[8 + w]; }
    float mean = S * (1.f / HID);
    float var  = S2 * (1.f / HID) - mean * mean;
    float rstd = rsqrtf(var + EPS);
    const float* mrow = mod + b * MODW;
    __half* orow = out + (size_t)row * HID;
    for (int i = tid; i < HID; i += 256) {
        float v = (buf[i] - mean) * rstd;
        orow[i] = __float2half(fmaf(v, 1.f + mrow[scOff + i], mrow[shOff + i]));
    }
}

// --------------- kernel 3: per-head LN of q and k (in place) ---------------
__global__ __launch_bounds__(256) void qkln_kernel(
    float* __restrict__ qkv, const float* __restrict__ g_q,
    const float* __restrict__ g_k)
{
    int warp = blockIdx.x * 8 + (threadIdx.x >> 5);
    int lane = threadIdx.x & 31;
    int h  = warp & 15;
    int qk = (warp >> 4) & 1;
    int bn = warp >> 5;
    float* p = qkv + (size_t)bn * (3 * HID) + qk * HID + h * HD;
    float v0 = p[lane];
    float v1 = p[lane + 32];
    float v2 = (lane < 8) ? p[lane + 64] : 0.f;
    float s  = v0 + v1 + v2;
    float s2 = v0 * v0 + v1 * v1 + v2 * v2;
    #pragma unroll
    for (int o = 16; o; o >>= 1) {
        s  += __shfl_xor_sync(0xffffffffu, s,  o);
        s2 += __shfl_xor_sync(0xffffffffu, s2, o);
    }
    float mean = s * (1.f / HD);
    float var  = s2 * (1.f / HD) - mean * mean;
    float rstd = rsqrtf(var + EPS);
    const float* g = qk ? g_k : g_q;
    p[lane]      = (v0 - mean) * rstd * g[lane];
    p[lane + 32] = (v1 - mean) * rstd * g[lane + 32];
    if (lane < 8) p[lane + 64] = (v2 - mean) * rstd * g[lane + 64];
}

// --------------- kernel 4: flash attention (tf32 mma.sync), fp16 out --------
#define AQ 128
#define AK 64
#define QST 76
#define PST 68
#define ATTN_SMEM ((AQ * QST + 2 * AK * QST + AQ * PST) * 4)

__global__ __launch_bounds__(256) void attn_kernel(
    const float* __restrict__ qkv, __half* __restrict__ o)
{
    extern __shared__ float sm[];
    float* qs = sm;                    // [128][76]
    float* ks = qs + AQ * QST;         // [64][76]
    float* vs = ks + AK * QST;         // [64][76]
    float* ps = vs + AK * QST;         // [128][68]

    int tid = threadIdx.x;
    int lane = tid & 31;
    int warp = tid >> 5;
    int grp = lane >> 2;
    int t4 = lane & 3;
    int m0 = warp * 16;

    int q0 = blockIdx.x * AQ;
    int h = blockIdx.y, b = blockIdx.z;
    const size_t baseBN = (size_t)b * SEQ * (3 * HID);
    const int hoff = h * HD;
    const float scale = 0.11785113019775793f;

    for (int idx = tid; idx < AQ * 18; idx += 256) {
        int r = idx / 18, d4 = (idx - r * 18) * 4;
        float4 v = *(const float4*)(qkv + baseBN + (size_t)(q0 + r) * (3 * HID) + hoff + d4);
        *(float4*)(qs + r * QST + d4) = v;
    }

    float accO[9][4];
    #pragma unroll
    for (int di = 0; di < 9; ++di)
        #pragma unroll
        for (int e = 0; e < 4; ++e) accO[di][e] = 0.f;
    float mi0 = -INFINITY, mi1 = -INFINITY;
    float li0 = 0.f, li1 = 0.f;

    for (int kt = 0; kt < SEQ / AK; ++kt) {
        __syncthreads();
        int k0 = kt * AK;
        for (int idx = tid; idx < AK * 18; idx += 256) {
            int r = idx / 18, d4 = (idx - r * 18) * 4;
            size_t base = baseBN + (size_t)(k0 + r) * (3 * HID) + hoff + d4;
            *(float4*)(ks + r * QST + d4) = *(const float4*)(qkv + base + HID);
            *(float4*)(vs + r * QST + d4) = *(const float4*)(qkv + base + 2 * HID);
        }
        __syncthreads();

        float sacc[8][4];
        #pragma unroll
        for (int ni = 0; ni < 8; ++ni)
            #pragma unroll
            for (int e = 0; e < 4; ++e) sacc[ni][e] = 0.f;
        #pragma unroll
        for (int k8 = 0; k8 < 72; k8 += 8) {
            unsigned a0 = __float_as_uint(qs[(m0 + grp) * QST + k8 + t4]);
            unsigned a1 = __float_as_uint(qs[(m0 + grp + 8) * QST + k8 + t4]);
            unsigned a2 = __float_as_uint(qs[(m0 + grp) * QST + k8 + t4 + 4]);
            unsigned a3 = __float_as_uint(qs[(m0 + grp + 8) * QST + k8 + t4 + 4]);
            #pragma unroll
            for (int ni = 0; ni < 8; ++ni) {
                unsigned b0 = __float_as_uint(ks[(ni * 8 + grp) * QST + k8 + t4]);
                unsigned b1 = __float_as_uint(ks[(ni * 8 + grp) * QST + k8 + t4 + 4]);
                mma_tf32(sacc[ni][0], sacc[ni][1], sacc[ni][2], sacc[ni][3],
                         a0, a1, a2, a3, b0, b1);
            }
        }

        float rmax0 = -INFINITY, rmax1 = -INFINITY;
        #pragma unroll
        for (int ni = 0; ni < 8; ++ni) {
            sacc[ni][0] *= scale; sacc[ni][1] *= scale;
            sacc[ni][2] *= scale; sacc[ni][3] *= scale;
            rmax0 = fmaxf(rmax0, fmaxf(sacc[ni][0], sacc[ni][1]));
            rmax1 = fmaxf(rmax1, fmaxf(sacc[ni][2], sacc[ni][3]));
        }
        #pragma unroll
        for (int off = 1; off < 4; off <<= 1) {
            rmax0 = fmaxf(rmax0, __shfl_xor_sync(0xffffffffu, rmax0, off));
            rmax1 = fmaxf(rmax1, __shfl_xor_sync(0xffffffffu, rmax1, off));
        }
        float newm0 = fmaxf(mi0, rmax0);
        float newm1 = fmaxf(mi1, rmax1);
        float alpha0 = __expf(mi0 - newm0);
        float alpha1 = __expf(mi1 - newm1);
        mi0 = newm0; mi1 = newm1;
        float rsum0 = 0.f, rsum1 = 0.f;
        #pragma unroll
        for (int ni = 0; ni < 8; ++ni) {
            float p0 = to_tf32(__expf(sacc[ni][0] - newm0));
            float p1 = to_tf32(__expf(sacc[ni][1] - newm0));
            float p2 = to_tf32(__expf(sacc[ni][2] - newm1));
            float p3 = to_tf32(__expf(sacc[ni][3] - newm1));
            rsum0 += p0 + p1; rsum1 += p2 + p3;
            *(float2*)(ps + (m0 + grp) * PST + ni * 8 + t4 * 2) = make_float2(p0, p1);
            *(float2*)(ps + (m0 + grp + 8) * PST + ni * 8 + t4 * 2) = make_float2(p2, p3);
        }
        #pragma unroll
        for (int off = 1; off < 4; off <<= 1) {
            rsum0 += __shfl_xor_sync(0xffffffffu, rsum0, off);
            rsum1 += __shfl_xor_sync(0xffffffffu, rsum1, off);
        }
        li0 = li0 * alpha0 + rsum0;
        li1 = li1 * alpha1 + rsum1;
        #pragma unroll
        for (int di = 0; di < 9; ++di) {
            accO[di][0] *= alpha0; accO[di][1] *= alpha0;
            accO[di][2] *= alpha1; accO[di][3] *= alpha1;
        }
        __syncwarp();

        #pragma unroll
        for (int k8 = 0; k8 < 64; k8 += 8) {
            unsigned a0 = __float_as_uint(ps[(m0 + grp) * PST + k8 + t4]);
            unsigned a1 = __float_as_uint(ps[(m0 + grp + 8) * PST + k8 + t4]);
            unsigned a2 = __float_as_uint(ps[(m0 + grp) * PST + k8 + t4 + 4]);
            unsigned a3 = __float_as_uint(ps[(m0 + grp + 8) * PST + k8 + t4 + 4]);
            #pragma unroll
            for (int di = 0; di < 9; ++di) {
                unsigned b0 = __float_as_uint(vs[(k8 + t4) * QST + di * 8 + grp]);
                unsigned b1 = __float_as_uint(vs[(k8 + t4 + 4) * QST + di * 8 + grp]);
                mma_tf32(accO[di][0], accO[di][1], accO[di][2], accO[di][3],
                         a0, a1, a2, a3, b0, b1);
            }
        }
        __syncwarp();
    }

    float inv0 = 1.f / li0, inv1 = 1.f / li1;
    int row0 = q0 + m0 + grp;
    size_t b0a = ((size_t)b * SEQ + row0) * HID + hoff;
    size_t b1a = ((size_t)b * SEQ + row0 + 8) * HID + hoff;
    #pragma unroll
    for (int di = 0; di < 9; ++di) {
        int d = di * 8 + t4 * 2;
        *(__half2*)(o + b0a + d) = __floats2half2_rn(accO[di][0] * inv0, accO[di][1] * inv0);
        *(__half2*)(o + b1a + d) = __floats2half2_rn(accO[di][2] * inv1, accO[di][3] * inv1);
    }
}

// --------------- kernel 5: FP16 GEMM, cp.async 4-stage pipeline -------------
// A: [M][K] fp16; BT: [N][K] fp16 (pre-transposed). 128x128x32 tile,
// 8 warps each 64x32 (4x4 m16n8k16). EPI 0: fp32 +bias; 1: fp16 gelu;
// 2: fp32 res + gate*(..)
#define TBK 32
#define ASTRH 40                      // halves per smem row (conflict-free)
#define TILE_H_BYTES (128 * ASTRH * 2)    // 10240
#define NSTAGE 4
#define GEMM_SMEM (NSTAGE * 2 * TILE_H_BYTES)   // 81920

template <int EPI, typename OutT>
__global__ __launch_bounds__(256) void hgemm_kernel(
    const __half* __restrict__ A, const __half* __restrict__ BT,
    const float* __restrict__ bias, const float* __restrict__ res,
    const float* __restrict__ gate, OutT* __restrict__ C,
    int M, int N, int K)
{
    extern __shared__ char smc[];
    uint32_t sbase = smem_u32(smc);
    __half* As = (__half*)smc;                         // [NSTAGE][128][ASTRH]
    __half* Bs = (__half*)(smc + NSTAGE * TILE_H_BYTES);

    int tid = threadIdx.x;
    int lane = tid & 31;
    int warp = tid >> 5;
    int m0 = (warp & 1) * 64;
    int n0 = (warp >> 1) * 32;
    int grp = lane >> 2;
    int t4 = lane & 3;

    int cRow = blockIdx.y, cCol = blockIdx.x;
    const __half* Ab = A + (size_t)cRow * 128 * K;
    const __half* Bb = BT + (size_t)cCol * 128 * K;

    float acc[4][4][4];
    #pragma unroll
    for (int mi = 0; mi < 4; ++mi)
        #pragma unroll
        for (int ni = 0; ni < 4; ++ni)
            #pragma unroll
            for (int e = 0; e < 4; ++e) acc[mi][ni][e] = 0.f;

    int KT = K / TBK;

    // stage loader: A 512 chunks of 16B + B 512 chunks -> 4 cp.async/thread
    auto load_stage = [&](int kt, int s) {
        uint32_t aBase = sbase + s * TILE_H_BYTES;
        uint32_t bBase = sbase + (NSTAGE + s) * TILE_H_BYTES;
        const __half* Asrc = Ab + kt * TBK;
        const __half* Bsrc = Bb + kt * TBK;
        #pragma unroll
        for (int j = 0; j < 2; ++j) {
            int idx = tid + j * 256;
            int r = idx >> 2, c = idx & 3;
            cp16s(aBase + r * (ASTRH * 2) + c * 16, Asrc + (size_t)r * K + c * 8);
            cp16s(bBase + r * (ASTRH * 2) + c * 16, Bsrc + (size_t)r * K + c * 8);
        }
    };

    #pragma unroll
    for (int s = 0; s < NSTAGE - 1; ++s) {
        load_stage(s, s);
        cp_commit();
    }

    for (int kt = 0; kt < KT; ++kt) {
        cp_wait<NSTAGE - 2>();
        __syncthreads();

        int pf = kt + NSTAGE - 1;
        if (pf < KT) load_stage(pf, pf & (NSTAGE - 1));
        cp_commit();

        const __half* Asc = As + (size_t)(kt & (NSTAGE - 1)) * 128 * ASTRH;
        const __half* Bsc = Bs + (size_t)(kt & (NSTAGE - 1)) * 128 * ASTRH;
        #pragma unroll
        for (int ks = 0; ks < 2; ++ks) {
            int k16 = ks * 16;
            unsigned af[4][4], bf[4][2];
            #pragma unroll
            for (int mi = 0; mi < 4; ++mi) {
                int r = m0 + mi * 16 + grp;
                af[mi][0] = *(const unsigned*)(Asc + r * ASTRH + k16 + t4 * 2);
                af[mi][1] = *(const unsigned*)(Asc + (r + 8) * ASTRH + k16 + t4 * 2);
                af[mi][2] = *(const unsigned*)(Asc + r * ASTRH + k16 + t4 * 2 + 8);
                af[mi][3] = *(const unsigned*)(Asc + (r + 8) * ASTRH + k16 + t4 * 2 + 8);
            }
            #pragma unroll
            for (int ni = 0; ni < 4; ++ni) {
                int cc = n0 + ni * 8 + grp;
                bf[ni][0] = *(const unsigned*)(Bsc + cc * ASTRH + k16 + t4 * 2);
                bf[ni][1] = *(const unsigned*)(Bsc + cc * ASTRH + k16 + t4 * 2 + 8);
            }
            #pragma unroll
            for (int mi = 0; mi < 4; ++mi)
                #pragma unroll
                for (int ni = 0; ni < 4; ++ni)
                    mma_f16(acc[mi][ni][0], acc[mi][ni][1], acc[mi][ni][2], acc[mi][ni][3],
                            af[mi][0], af[mi][1], af[mi][2], af[mi][3],
                            bf[ni][0], bf[ni][1]);
        }
    }

    // ---- epilogue ----
    #pragma unroll
    for (int mi = 0; mi < 4; ++mi) {
        #pragma unroll
        for (int half_ = 0; half_ < 2; ++half_) {
            int row = cRow * 128 + m0 + mi * 16 + grp + half_ * 8;
            int gb = (row >> 10) * MODW;
            #pragma unroll
            for (int ni = 0; ni < 4; ++ni) {
                int col = cCol * 128 + n0 + ni * 8 + t4 * 2;
                float v0 = acc[mi][ni][half_ * 2 + 0] + bias[col];
                float v1 = acc[mi][ni][half_ * 2 + 1] + bias[col + 1];
                if (EPI == 1) {
                    float i0 = 0.7978845608028654f * (v0 + 0.044715f * v0 * v0 * v0);
                    float i1 = 0.7978845608028654f * (v1 + 0.044715f * v1 * v1 * v1);
                    v0 = v0 / (1.f + __expf(-2.f * i0));
                    v1 = v1 / (1.f + __expf(-2.f * i1));
                } else if (EPI == 2) {
                    v0 = fmaf(gate[gb + col],     v0, res[(size_t)row * N + col]);
                    v1 = fmaf(gate[gb + col + 1], v1, res[(size_t)row * N + col + 1]);
                }
                OutT* dst = C + (size_t)row * N + col;
                if (sizeof(OutT) == 2) {
                    *(__half2*)dst = __floats2half2_rn(v0, v1);
                } else {
                    *(float2*)dst = make_float2(v0, v1);
                }
            }
        }
    }
}

// ---------------------------- launcher --------------------------------------
extern "C" void kernel_launch(void* const* d_in, const int* in_sizes, int n_in,
                              void* d_out, int out_size)
{
    const float* x      = (const float*)d_in[0];
    const float* c      = (const float*)d_in[1];
    const float* w_mod  = (const float*)d_in[2];
    const float* b_mod  = (const float*)d_in[3];
    const float* w_qkv  = (const float*)d_in[4];
    const float* b_qkv  = (const float*)d_in[5];
    const float* gq     = (const float*)d_in[6];
    const float* gk     = (const float*)d_in[7];
    const float* w_proj = (const float*)d_in[8];
    const float* b_proj = (const float*)d_in[9];
    const float* w1     = (const float*)d_in[10];
    const float* b1     = (const float*)d_in[11];
    const float* w2     = (const float*)d_in[12];
    const float* b2     = (const float*)d_in[13];
    float* out = (float*)d_out;

    float *p_mod, *p_qkv, *p_x1;
    __half *p_xn16, *p_o16, *p_h16, *p_wqkvT, *p_wprojT, *p_w1T, *p_w2T;
    cudaGetSymbolAddress((void**)&p_mod, g_mod);
    cudaGetSymbolAddress((void**)&p_xn16, g_xn16);
    cudaGetSymbolAddress((void**)&p_qkv, g_qkv);
    cudaGetSymbolAddress((void**)&p_o16, g_o16);
    cudaGetSymbolAddress((void**)&p_x1,  g_x1);
    cudaGetSymbolAddress((void**)&p_h16, g_h16);
    cudaGetSymbolAddress((void**)&p_wqkvT, g_wqkvT16);
    cudaGetSymbolAddress((void**)&p_wprojT, g_wprojT16);
    cudaGetSymbolAddress((void**)&p_w1T, g_w1T16);
    cudaGetSymbolAddress((void**)&p_w2T, g_w2T16);

    cudaFuncSetAttribute(attn_kernel,
                         cudaFuncAttributeMaxDynamicSharedMemorySize, ATTN_SMEM);
    cudaFuncSetAttribute(hgemm_kernel<0, float>,
                         cudaFuncAttributeMaxDynamicSharedMemorySize, GEMM_SMEM);
    cudaFuncSetAttribute(hgemm_kernel<1, __half>,
                         cudaFuncAttributeMaxDynamicSharedMemorySize, GEMM_SMEM);
    cudaFuncSetAttribute(hgemm_kernel<2, float>,
                         cudaFuncAttributeMaxDynamicSharedMemorySize, GEMM_SMEM);

    // 0. convert+transpose weights to fp16 [N][K]
    wcvt_kernel<<<dim3(3 * HID / 32, HID / 32), 256>>>(w_qkv, p_wqkvT, HID, 3 * HID);
    wcvt_kernel<<<dim3(HID / 32, HID / 32), 256>>>(w_proj, p_wprojT, HID, HID);
    wcvt_kernel<<<dim3(MLPD / 32, HID / 32), 256>>>(w1, p_w1T, HID, MLPD);
    wcvt_kernel<<<dim3(HID / 32, MLPD / 32), 256>>>(w2, p_w2T, MLPD, HID);

    // 1. adaLN modulation
    mod_kernel<<<dim3(MODW / 128, Bsz), 128>>>(c, w_mod, b_mod, p_mod);
    // 2. LN + modulate (MSA) -> fp16
    ln_mod_kernel<<<ROWS, 256>>>(x, p_mod, 0, HID, p_xn16);
    // 3. QKV GEMM (fp16 in, fp32 out)
    hgemm_kernel<0, float><<<dim3(3 * HID / 128, ROWS / 128), 256, GEMM_SMEM>>>(
        p_xn16, p_wqkvT, b_qkv, nullptr, nullptr, p_qkv, ROWS, 3 * HID, HID);
    // 4. per-head LN of q,k (fp32 in place)
    qkln_kernel<<<ROWS * 32 / 8, 256>>>(p_qkv, gq, gk);
    // 5. attention -> fp16 o
    attn_kernel<<<dim3(SEQ / AQ, NH, Bsz), 256, ATTN_SMEM>>>(p_qkv, p_o16);
    // 6. proj + gated residual -> fp32 x1
    hgemm_kernel<2, float><<<dim3(HID / 128, ROWS / 128), 256, GEMM_SMEM>>>(
        p_o16, p_wprojT, b_proj, x, p_mod + 2 * HID, p_x1, ROWS, HID, HID);
    // 7. LN + modulate (MLP) -> fp16
    ln_mod_kernel<<<ROWS, 256>>>(p_x1, p_mod, 3 * HID, 4 * HID, p_xn16);
    // 8. MLP up + gelu -> fp16 h
    hgemm_kernel<1, __half><<<dim3(MLPD / 128, ROWS / 128), 256, GEMM_SMEM>>>(
        p_xn16, p_w1T, b1, nullptr, nullptr, p_h16, ROWS, MLPD, HID);
    // 9. MLP down + gated residual -> fp32 out
    hgemm_kernel<2, float><<<dim3(HID / 128, ROWS / 128), 256, GEMM_SMEM>>>(
        p_h16, p_w2T, b2, p_x1, p_mod + 5 * HID, out, ROWS, HID, MLPD);
}

// round 6
// speedup vs baseline: 5.2177x; 1.0987x over previous
#include <cuda_runtime.h>
#include <cuda_fp16.h>
#include <math.h>
#include <stdint.h>

// Problem constants
#define Bsz 16
#define SEQ 1024
#define HID 1152
#define NH 16
#define HD 72
#define MLPD 4608
#define ROWS (Bsz * SEQ)          // 16384
#define MODW (6 * HID)            // 6912
#define EPS 1e-6f

// ---------------- scratch (device globals; allocation-free) ----------------
__device__ float  g_mod[Bsz * MODW];
__device__ __half g_xn16[ROWS * HID];
__device__ __half g_qkv16[ROWS * 3 * HID];
__device__ __half g_o16[ROWS * HID];
__device__ float  g_x1[ROWS * HID];
__device__ __half g_h16[ROWS * MLPD];
// fp16 transposed weights [N][K]
__device__ __half g_wqkvT16[3 * HID * HID];
__device__ __half g_wprojT16[HID * HID];
__device__ __half g_w1T16[HID * MLPD];
__device__ __half g_w2T16[MLPD * HID];

__device__ __forceinline__ void mma_f16(
    float& c0, float& c1, float& c2, float& c3,
    unsigned a0, unsigned a1, unsigned a2, unsigned a3,
    unsigned b0, unsigned b1)
{
    asm volatile(
        "mma.sync.aligned.m16n8k16.row.col.f32.f16.f16.f32 "
        "{%0,%1,%2,%3}, {%4,%5,%6,%7}, {%8,%9}, {%0,%1,%2,%3};"
        : "+f"(c0), "+f"(c1), "+f"(c2), "+f"(c3)
        : "r"(a0), "r"(a1), "r"(a2), "r"(a3), "r"(b0), "r"(b1));
}

__device__ __forceinline__ void cp16s(uint32_t dst, const void* src) {
    asm volatile("cp.async.cg.shared.global [%0], [%1], 16;" :: "r"(dst), "l"(src));
}
__device__ __forceinline__ void cp_commit() {
    asm volatile("cp.async.commit_group;");
}
template <int N> __device__ __forceinline__ void cp_wait() {
    asm volatile("cp.async.wait_group %0;" :: "n"(N));
}
__device__ __forceinline__ uint32_t smem_u32(const void* p) {
    uint32_t a;
    asm("{ .reg .u64 t; cvta.to.shared.u64 t, %1; cvt.u32.u64 %0, t; }"
        : "=r"(a) : "l"(p));
    return a;
}
__device__ __forceinline__ unsigned h2u(__half2 h) {
    return *reinterpret_cast<unsigned*>(&h);
}

// ------- kernel 0: weight convert+transpose fp32 [K][N] -> fp16 [N][K] ------
__global__ __launch_bounds__(256) void wcvt_kernel(
    const float* __restrict__ w, __half* __restrict__ wt, int K, int N)
{
    __shared__ float t[32][33];
    int n0 = blockIdx.x * 32, k0 = blockIdx.y * 32;
    int tx = threadIdx.x & 31, ty = threadIdx.x >> 5;
    #pragma unroll
    for (int j = 0; j < 32; j += 8)
        t[ty + j][tx] = w[(size_t)(k0 + ty + j) * N + n0 + tx];
    __syncthreads();
    #pragma unroll
    for (int j = 0; j < 32; j += 8)
        wt[(size_t)(n0 + ty + j) * K + k0 + tx] = __float2half(t[tx][ty + j]);
}

// ---------------- kernel 1: mod = swish(c) @ w_mod + b_mod ----------------
__global__ __launch_bounds__(128) void mod_kernel(
    const float* __restrict__ c, const float* __restrict__ w_mod,
    const float* __restrict__ b_mod, float* __restrict__ mod)
{
    __shared__ float sc[HID];
    int b = blockIdx.y;
    for (int i = threadIdx.x; i < HID; i += blockDim.x) {
        float v = c[b * HID + i];
        sc[i] = v / (1.0f + expf(-v));
    }
    __syncthreads();
    int col = blockIdx.x * blockDim.x + threadIdx.x;
    float acc = b_mod[col];
    #pragma unroll 4
    for (int k = 0; k < HID; ++k)
        acc = fmaf(sc[k], w_mod[(size_t)k * MODW + col], acc);
    mod[b * MODW + col] = acc;
}

// --------- kernel 2: LN(x) * (1+sc) + sh  (per row), fp16 output ------------
__global__ __launch_bounds__(256) void ln_mod_kernel(
    const float* __restrict__ x, const float* __restrict__ mod,
    int shOff, int scOff, __half* __restrict__ out)
{
    __shared__ float buf[HID];
    __shared__ float red[16];
    int row = blockIdx.x;
    int b = row >> 10;
    int tid = threadIdx.x;
    const float* xr = x + (size_t)row * HID;
    float s = 0.f, s2 = 0.f;
    for (int i = tid; i < HID; i += 256) {
        float v = xr[i];
        buf[i] = v;
        s += v; s2 += v * v;
    }
    #pragma unroll
    for (int o = 16; o; o >>= 1) {
        s  += __shfl_xor_sync(0xffffffffu, s,  o);
        s2 += __shfl_xor_sync(0xffffffffu, s2, o);
    }
    if ((tid & 31) == 0) { red[tid >> 5] = s; red[8 + (tid >> 5)] = s2; }
    __syncthreads();
    float S = 0.f, S2 = 0.f;
    #pragma unroll
    for (int w = 0; w < 8; ++w) { S += red[w]; S2 += red[8 + w]; }
    float mean = S * (1.f / HID);
    float var  = S2 * (1.f / HID) - mean * mean;
    float rstd = rsqrtf(var + EPS);
    const float* mrow = mod + b * MODW;
    __half* orow = out + (size_t)row * HID;
    for (int i = tid; i < HID; i += 256) {
        float v = (buf[i] - mean) * rstd;
        orow[i] = __float2half(fmaf(v, 1.f + mrow[scOff + i], mrow[shOff + i]));
    }
}

// --------------- kernel 3: per-head LN of q and k (fp16 in place) -----------
__global__ __launch_bounds__(256) void qkln_kernel(
    __half* __restrict__ qkv, const float* __restrict__ g_q,
    const float* __restrict__ g_k)
{
    int warp = blockIdx.x * 8 + (threadIdx.x >> 5);
    int lane = threadIdx.x & 31;
    int h  = warp & 15;
    int qk = (warp >> 4) & 1;
    int bn = warp >> 5;
    __half* p = qkv + (size_t)bn * (3 * HID) + qk * HID + h * HD;
    float v0 = __half2float(p[lane]);
    float v1 = __half2float(p[lane + 32]);
    float v2 = (lane < 8) ? __half2float(p[lane + 64]) : 0.f;
    float s  = v0 + v1 + v2;
    float s2 = v0 * v0 + v1 * v1 + v2 * v2;
    #pragma unroll
    for (int o = 16; o; o >>= 1) {
        s  += __shfl_xor_sync(0xffffffffu, s,  o);
        s2 += __shfl_xor_sync(0xffffffffu, s2, o);
    }
    float mean = s * (1.f / HD);
    float var  = s2 * (1.f / HD) - mean * mean;
    float rstd = rsqrtf(var + EPS);
    const float* g = qk ? g_k : g_q;
    p[lane]      = __float2half((v0 - mean) * rstd * g[lane]);
    p[lane + 32] = __float2half((v1 - mean) * rstd * g[lane + 32]);
    if (lane < 8) p[lane + 64] = __float2half((v2 - mean) * rstd * g[lane + 64]);
}

// --------------- kernel 4: flash attention (fp16 mma, FA2 repack) -----------
// BQ=128, BK=64, 8 warps; warp w owns queries [w*16, w*16+16).
// S via m16n8k16 (dim padded 72->80), P stays in registers -> PV directly.
#define AQ 128
#define AK 64
#define QH 88     // halves stride for qs/ks (conflict-free: 44 words/row)
#define VH 72     // halves stride for vst (36 words/row, conflict-free)
#define ATTN_SMEM ((AQ * QH + AK * QH + HD * VH) * 2)

__global__ __launch_bounds__(256) void attn_kernel(
    const __half* __restrict__ qkv, __half* __restrict__ o)
{
    extern __shared__ __half smh[];
    __half* qs  = smh;                 // [128][88]
    __half* ks  = qs + AQ * QH;        // [64][88]
    __half* vst = ks + AK * QH;        // [72][72]  (dim-major)

    int tid = threadIdx.x;
    int lane = tid & 31;
    int warp = tid >> 5;
    int grp = lane >> 2;
    int t4 = lane & 3;
    int m0 = warp * 16;

    int q0 = blockIdx.x * AQ;
    int h = blockIdx.y, b = blockIdx.z;
    const size_t baseBN = (size_t)b * SEQ * (3 * HID);
    const int hoff = h * HD;
    const float scale = 0.11785113019775793f;   // 1/sqrt(72)

    // load Q tile: 9 x 16B chunks per row
    for (int idx = tid; idx < AQ * 9; idx += 256) {
        int r = idx / 9, c = (idx - r * 9) * 8;
        *(float4*)(qs + r * QH + c) =
            *(const float4*)(qkv + baseBN + (size_t)(q0 + r) * (3 * HID) + hoff + c);
    }
    // zero pad cols 72..79 of qs and ks (read by the k16=64 step)
    for (int idx = tid; idx < AQ + AK; idx += 256) {
        __half* base = (idx < AQ) ? (qs + idx * QH) : (ks + (idx - AQ) * QH);
        *(float4*)(base + 72) = make_float4(0.f, 0.f, 0.f, 0.f);
    }

    float accO[9][4];
    #pragma unroll
    for (int di = 0; di < 9; ++di)
        #pragma unroll
        for (int e = 0; e < 4; ++e) accO[di][e] = 0.f;
    float mi0 = -INFINITY, mi1 = -INFINITY;
    float li0 = 0.f, li1 = 0.f;

    for (int kt = 0; kt < SEQ / AK; ++kt) {
        __syncthreads();   // prior iter done reading ks/vst (and qs ready)
        int k0 = kt * AK;
        // K tile: row-major
        for (int idx = tid; idx < AK * 9; idx += 256) {
            int r = idx / 9, c = (idx - r * 9) * 8;
            *(float4*)(ks + r * QH + c) = *(const float4*)(
                qkv + baseBN + (size_t)(k0 + r) * (3 * HID) + HID + hoff + c);
        }
        // V tile: transposed to dim-major
        for (int idx = tid; idx < AK * 36; idx += 256) {
            int key = idx / 36, d2 = (idx - key * 36) * 2;
            __half2 v = *(const __half2*)(
                qkv + baseBN + (size_t)(k0 + key) * (3 * HID) + 2 * HID + hoff + d2);
            vst[d2 * VH + key]       = __low2half(v);
            vst[(d2 + 1) * VH + key] = __high2half(v);
        }
        __syncthreads();

        // ---- S = Q K^T : m16 x 64, 5 k16 steps ----
        float sacc[8][4];
        #pragma unroll
        for (int ni = 0; ni < 8; ++ni)
            #pragma unroll
            for (int e = 0; e < 4; ++e) sacc[ni][e] = 0.f;
        #pragma unroll
        for (int ksb = 0; ksb < 5; ++ksb) {
            int k16 = ksb * 16;
            unsigned a0 = *(const unsigned*)(qs + (m0 + grp) * QH + k16 + t4 * 2);
            unsigned a1 = *(const unsigned*)(qs + (m0 + grp + 8) * QH + k16 + t4 * 2);
            unsigned a2 = *(const unsigned*)(qs + (m0 + grp) * QH + k16 + t4 * 2 + 8);
            unsigned a3 = *(const unsigned*)(qs + (m0 + grp + 8) * QH + k16 + t4 * 2 + 8);
            #pragma unroll
            for (int ni = 0; ni < 8; ++ni) {
                unsigned b0 = *(const unsigned*)(ks + (ni * 8 + grp) * QH + k16 + t4 * 2);
                unsigned b1 = *(const unsigned*)(ks + (ni * 8 + grp) * QH + k16 + t4 * 2 + 8);
                mma_f16(sacc[ni][0], sacc[ni][1], sacc[ni][2], sacc[ni][3],
                        a0, a1, a2, a3, b0, b1);
            }
        }

        // ---- online softmax; P packed to fp16 fragments in registers ----
        float rmax0 = -INFINITY, rmax1 = -INFINITY;
        #pragma unroll
        for (int ni = 0; ni < 8; ++ni) {
            sacc[ni][0] *= scale; sacc[ni][1] *= scale;
            sacc[ni][2] *= scale; sacc[ni][3] *= scale;
            rmax0 = fmaxf(rmax0, fmaxf(sacc[ni][0], sacc[ni][1]));
            rmax1 = fmaxf(rmax1, fmaxf(sacc[ni][2], sacc[ni][3]));
        }
        #pragma unroll
        for (int off = 1; off < 4; off <<= 1) {
            rmax0 = fmaxf(rmax0, __shfl_xor_sync(0xffffffffu, rmax0, off));
            rmax1 = fmaxf(rmax1, __shfl_xor_sync(0xffffffffu, rmax1, off));
        }
        float newm0 = fmaxf(mi0, rmax0);
        float newm1 = fmaxf(mi1, rmax1);
        float alpha0 = __expf(mi0 - newm0);
        float alpha1 = __expf(mi1 - newm1);
        mi0 = newm0; mi1 = newm1;
        float rsum0 = 0.f, rsum1 = 0.f;
        unsigned ph0[8], ph1[8];   // P fragments: row grp / row grp+8
        #pragma unroll
        for (int ni = 0; ni < 8; ++ni) {
            float p0 = __expf(sacc[ni][0] - newm0);
            float p1 = __expf(sacc[ni][1] - newm0);
            float p2 = __expf(sacc[ni][2] - newm1);
            float p3 = __expf(sacc[ni][3] - newm1);
            rsum0 += p0 + p1; rsum1 += p2 + p3;
            ph0[ni] = h2u(__floats2half2_rn(p0, p1));
            ph1[ni] = h2u(__floats2half2_rn(p2, p3));
        }
        #pragma unroll
        for (int off = 1; off < 4; off <<= 1) {
            rsum0 += __shfl_xor_sync(0xffffffffu, rsum0, off);
            rsum1 += __shfl_xor_sync(0xffffffffu, rsum1, off);
        }
        li0 = li0 * alpha0 + rsum0;
        li1 = li1 * alpha1 + rsum1;
        #pragma unroll
        for (int di = 0; di < 9; ++di) {
            accO[di][0] *= alpha0; accO[di][1] *= alpha0;
            accO[di][2] *= alpha1; accO[di][3] *= alpha1;
        }

        // ---- O += P V : A = P fragments (registers), B = vst ----
        #pragma unroll
        for (int kb = 0; kb < 4; ++kb) {
            unsigned a0 = ph0[2 * kb],     a2 = ph0[2 * kb + 1];
            unsigned a1 = ph1[2 * kb],     a3 = ph1[2 * kb + 1];
            #pragma unroll
            for (int di = 0; di < 9; ++di) {
                unsigned b0 = *(const unsigned*)(vst + (di * 8 + grp) * VH + kb * 16 + t4 * 2);
                unsigned b1 = *(const unsigned*)(vst + (di * 8 + grp) * VH + kb * 16 + t4 * 2 + 8);
                mma_f16(accO[di][0], accO[di][1], accO[di][2], accO[di][3],
                        a0, a1, a2, a3, b0, b1);
            }
        }
    }

    // ---- write O (fp16) ----
    float inv0 = 1.f / li0, inv1 = 1.f / li1;
    int row0 = q0 + m0 + grp;
    size_t b0a = ((size_t)b * SEQ + row0) * HID + hoff;
    size_t b1a = ((size_t)b * SEQ + row0 + 8) * HID + hoff;
    #pragma unroll
    for (int di = 0; di < 9; ++di) {
        int d = di * 8 + t4 * 2;
        *(__half2*)(o + b0a + d) = __floats2half2_rn(accO[di][0] * inv0, accO[di][1] * inv0);
        *(__half2*)(o + b1a + d) = __floats2half2_rn(accO[di][2] * inv1, accO[di][3] * inv1);
    }
}

// --------------- kernel 5: FP16 GEMM, cp.async 4-stage pipeline -------------
#define TBK 32
#define ASTRH 40
#define TILE_H_BYTES (128 * ASTRH * 2)    // 10240
#define NSTAGE 4
#define GEMM_SMEM (NSTAGE * 2 * TILE_H_BYTES)   // 81920

template <int EPI, typename OutT>
__global__ __launch_bounds__(256) void hgemm_kernel(
    const __half* __restrict__ A, const __half* __restrict__ BT,
    const float* __restrict__ bias, const float* __restrict__ res,
    const float* __restrict__ gate, OutT* __restrict__ C,
    int M, int N, int K)
{
    extern __shared__ char smc[];
    uint32_t sbase = smem_u32(smc);
    __half* As = (__half*)smc;
    __half* Bs = (__half*)(smc + NSTAGE * TILE_H_BYTES);

    int tid = threadIdx.x;
    int lane = tid & 31;
    int warp = tid >> 5;
    int m0 = (warp & 1) * 64;
    int n0 = (warp >> 1) * 32;
    int grp = lane >> 2;
    int t4 = lane & 3;

    int cRow = blockIdx.y, cCol = blockIdx.x;
    const __half* Ab = A + (size_t)cRow * 128 * K;
    const __half* Bb = BT + (size_t)cCol * 128 * K;

    float acc[4][4][4];
    #pragma unroll
    for (int mi = 0; mi < 4; ++mi)
        #pragma unroll
        for (int ni = 0; ni < 4; ++ni)
            #pragma unroll
            for (int e = 0; e < 4; ++e) acc[mi][ni][e] = 0.f;

    int KT = K / TBK;

    auto load_stage = [&](int kt, int s) {
        uint32_t aBase = sbase + s * TILE_H_BYTES;
        uint32_t bBase = sbase + (NSTAGE + s) * TILE_H_BYTES;
        const __half* Asrc = Ab + kt * TBK;
        const __half* Bsrc = Bb + kt * TBK;
        #pragma unroll
        for (int j = 0; j < 2; ++j) {
            int idx = tid + j * 256;
            int r = idx >> 2, c = idx & 3;
            cp16s(aBase + r * (ASTRH * 2) + c * 16, Asrc + (size_t)r * K + c * 8);
            cp16s(bBase + r * (ASTRH * 2) + c * 16, Bsrc + (size_t)r * K + c * 8);
        }
    };

    #pragma unroll
    for (int s = 0; s < NSTAGE - 1; ++s) {
        load_stage(s, s);
        cp_commit();
    }

    for (int kt = 0; kt < KT; ++kt) {
        cp_wait<NSTAGE - 2>();
        __syncthreads();

        int pf = kt + NSTAGE - 1;
        if (pf < KT) load_stage(pf, pf & (NSTAGE - 1));
        cp_commit();

        const __half* Asc = As + (size_t)(kt & (NSTAGE - 1)) * 128 * ASTRH;
        const __half* Bsc = Bs + (size_t)(kt & (NSTAGE - 1)) * 128 * ASTRH;
        #pragma unroll
        for (int ks = 0; ks < 2; ++ks) {
            int k16 = ks * 16;
            unsigned af[4][4], bf[4][2];
            #pragma unroll
            for (int mi = 0; mi < 4; ++mi) {
                int r = m0 + mi * 16 + grp;
                af[mi][0] = *(const unsigned*)(Asc + r * ASTRH + k16 + t4 * 2);
                af[mi][1] = *(const unsigned*)(Asc + (r + 8) * ASTRH + k16 + t4 * 2);
                af[mi][2] = *(const unsigned*)(Asc + r * ASTRH + k16 + t4 * 2 + 8);
                af[mi][3] = *(const unsigned*)(Asc + (r + 8) * ASTRH + k16 + t4 * 2 + 8);
            }
            #pragma unroll
            for (int ni = 0; ni < 4; ++ni) {
                int cc = n0 + ni * 8 + grp;
                bf[ni][0] = *(const unsigned*)(Bsc + cc * ASTRH + k16 + t4 * 2);
                bf[ni][1] = *(const unsigned*)(Bsc + cc * ASTRH + k16 + t4 * 2 + 8);
            }
            #pragma unroll
            for (int mi = 0; mi < 4; ++mi)
                #pragma unroll
                for (int ni = 0; ni < 4; ++ni)
                    mma_f16(acc[mi][ni][0], acc[mi][ni][1], acc[mi][ni][2], acc[mi][ni][3],
                            af[mi][0], af[mi][1], af[mi][2], af[mi][3],
                            bf[ni][0], bf[ni][1]);
        }
    }

    // ---- epilogue ----
    #pragma unroll
    for (int mi = 0; mi < 4; ++mi) {
        #pragma unroll
        for (int half_ = 0; half_ < 2; ++half_) {
            int row = cRow * 128 + m0 + mi * 16 + grp + half_ * 8;
            int gb = (row >> 10) * MODW;
            #pragma unroll
            for (int ni = 0; ni < 4; ++ni) {
                int col = cCol * 128 + n0 + ni * 8 + t4 * 2;
                float v0 = acc[mi][ni][half_ * 2 + 0] + bias[col];
                float v1 = acc[mi][ni][half_ * 2 + 1] + bias[col + 1];
                if (EPI == 1) {
                    float i0 = 0.7978845608028654f * (v0 + 0.044715f * v0 * v0 * v0);
                    float i1 = 0.7978845608028654f * (v1 + 0.044715f * v1 * v1 * v1);
                    v0 = v0 / (1.f + __expf(-2.f * i0));
                    v1 = v1 / (1.f + __expf(-2.f * i1));
                } else if (EPI == 2) {
                    v0 = fmaf(gate[gb + col],     v0, res[(size_t)row * N + col]);
                    v1 = fmaf(gate[gb + col + 1], v1, res[(size_t)row * N + col + 1]);
                }
                OutT* dst = C + (size_t)row * N + col;
                if (sizeof(OutT) == 2) {
                    *(__half2*)dst = __floats2half2_rn(v0, v1);
                } else {
                    *(float2*)dst = make_float2(v0, v1);
                }
            }
        }
    }
}

// ---------------------------- launcher --------------------------------------
extern "C" void kernel_launch(void* const* d_in, const int* in_sizes, int n_in,
                              void* d_out, int out_size)
{
    const float* x      = (const float*)d_in[0];
    const float* c      = (const float*)d_in[1];
    const float* w_mod  = (const float*)d_in[2];
    const float* b_mod  = (const float*)d_in[3];
    const float* w_qkv  = (const float*)d_in[4];
    const float* b_qkv  = (const float*)d_in[5];
    const float* gq     = (const float*)d_in[6];
    const float* gk     = (const float*)d_in[7];
    const float* w_proj = (const float*)d_in[8];
    const float* b_proj = (const float*)d_in[9];
    const float* w1     = (const float*)d_in[10];
    const float* b1     = (const float*)d_in[11];
    const float* w2     = (const float*)d_in[12];
    const float* b2     = (const float*)d_in[13];
    float* out = (float*)d_out;

    float *p_mod, *p_x1;
    __half *p_xn16, *p_qkv16, *p_o16, *p_h16, *p_wqkvT, *p_wprojT, *p_w1T, *p_w2T;
    cudaGetSymbolAddress((void**)&p_mod, g_mod);
    cudaGetSymbolAddress((void**)&p_xn16, g_xn16);
    cudaGetSymbolAddress((void**)&p_qkv16, g_qkv16);
    cudaGetSymbolAddress((void**)&p_o16, g_o16);
    cudaGetSymbolAddress((void**)&p_x1,  g_x1);
    cudaGetSymbolAddress((void**)&p_h16, g_h16);
    cudaGetSymbolAddress((void**)&p_wqkvT, g_wqkvT16);
    cudaGetSymbolAddress((void**)&p_wprojT, g_wprojT16);
    cudaGetSymbolAddress((void**)&p_w1T, g_w1T16);
    cudaGetSymbolAddress((void**)&p_w2T, g_w2T16);

    cudaFuncSetAttribute(attn_kernel,
                         cudaFuncAttributeMaxDynamicSharedMemorySize, ATTN_SMEM);
    cudaFuncSetAttribute(hgemm_kernel<0, __half>,
                         cudaFuncAttributeMaxDynamicSharedMemorySize, GEMM_SMEM);
    cudaFuncSetAttribute(hgemm_kernel<1, __half>,
                         cudaFuncAttributeMaxDynamicSharedMemorySize, GEMM_SMEM);
    cudaFuncSetAttribute(hgemm_kernel<2, float>,
                         cudaFuncAttributeMaxDynamicSharedMemorySize, GEMM_SMEM);

    // 0. convert+transpose weights to fp16 [N][K]
    wcvt_kernel<<<dim3(3 * HID / 32, HID / 32), 256>>>(w_qkv, p_wqkvT, HID, 3 * HID);
    wcvt_kernel<<<dim3(HID / 32, HID / 32), 256>>>(w_proj, p_wprojT, HID, HID);
    wcvt_kernel<<<dim3(MLPD / 32, HID / 32), 256>>>(w1, p_w1T, HID, MLPD);
    wcvt_kernel<<<dim3(HID / 32, MLPD / 32), 256>>>(w2, p_w2T, MLPD, HID);

    // 1. adaLN modulation
    mod_kernel<<<dim3(MODW / 128, Bsz), 128>>>(c, w_mod, b_mod, p_mod);
    // 2. LN + modulate (MSA) -> fp16
    ln_mod_kernel<<<ROWS, 256>>>(x, p_mod, 0, HID, p_xn16);
    // 3. QKV GEMM -> fp16 qkv
    hgemm_kernel<0, __half><<<dim3(3 * HID / 128, ROWS / 128), 256, GEMM_SMEM>>>(
        p_xn16, p_wqkvT, b_qkv, nullptr, nullptr, p_qkv16, ROWS, 3 * HID, HID);
    // 4. per-head LN of q,k (fp16 in place)
    qkln_kernel<<<ROWS * 32 / 8, 256>>>(p_qkv16, gq, gk);
    // 5. attention (full fp16) -> fp16 o
    attn_kernel<<<dim3(SEQ / AQ, NH, Bsz), 256, ATTN_SMEM>>>(p_qkv16, p_o16);
    // 6. proj + gated residual -> fp32 x1
    hgemm_kernel<2, float><<<dim3(HID / 128, ROWS / 128), 256, GEMM_SMEM>>>(
        p_o16, p_wprojT, b_proj, x, p_mod + 2 * HID, p_x1, ROWS, HID, HID);
    // 7. LN + modulate (MLP) -> fp16
    ln_mod_kernel<<<ROWS, 256>>>(p_x1, p_mod, 3 * HID, 4 * HID, p_xn16);
    // 8. MLP up + gelu -> fp16 h
    hgemm_kernel<1, __half><<<dim3(MLPD / 128, ROWS / 128), 256, GEMM_SMEM>>>(
        p_xn16, p_w1T, b1, nullptr, nullptr, p_h16, ROWS, MLPD, HID);
    // 9. MLP down + gated residual -> fp32 out
    hgemm_kernel<2, float><<<dim3(HID / 128, ROWS / 128), 256, GEMM_SMEM>>>(
        p_h16, p_w2T, b2, p_x1, p_mod + 5 * HID, out, ROWS, HID, MLPD);
}

// round 7
// speedup vs baseline: 5.7081x; 1.0940x over previous
#include <cuda_runtime.h>
#include <cuda_fp16.h>
#include <math.h>
#include <stdint.h>

// Problem constants
#define Bsz 16
#define SEQ 1024
#define HID 1152
#define NH 16
#define HD 72
#define MLPD 4608
#define ROWS (Bsz * SEQ)          // 16384
#define MODW (6 * HID)            // 6912
#define EPS 1e-6f

// ---------------- scratch (device globals; allocation-free) ----------------
__device__ float  g_mod[Bsz * MODW];
__device__ __half g_xn16[ROWS * HID];
__device__ __half g_qkv16[ROWS * 3 * HID];
__device__ __half g_o16[ROWS * HID];
__device__ float  g_x1[ROWS * HID];
__device__ __half g_h16[ROWS * MLPD];
// fp16 transposed weights [N][K]
__device__ __half g_wqkvT16[3 * HID * HID];
__device__ __half g_wprojT16[HID * HID];
__device__ __half g_w1T16[HID * MLPD];
__device__ __half g_w2T16[MLPD * HID];

__device__ __forceinline__ void mma_f16(
    float& c0, float& c1, float& c2, float& c3,
    unsigned a0, unsigned a1, unsigned a2, unsigned a3,
    unsigned b0, unsigned b1)
{
    asm volatile(
        "mma.sync.aligned.m16n8k16.row.col.f32.f16.f16.f32 "
        "{%0,%1,%2,%3}, {%4,%5,%6,%7}, {%8,%9}, {%0,%1,%2,%3};"
        : "+f"(c0), "+f"(c1), "+f"(c2), "+f"(c3)
        : "r"(a0), "r"(a1), "r"(a2), "r"(a3), "r"(b0), "r"(b1));
}

__device__ __forceinline__ void ldsm_x4(
    unsigned& r0, unsigned& r1, unsigned& r2, unsigned& r3, uint32_t addr)
{
    asm volatile("ldmatrix.sync.aligned.m8n8.x4.shared.b16 {%0,%1,%2,%3}, [%4];"
                 : "=r"(r0), "=r"(r1), "=r"(r2), "=r"(r3) : "r"(addr));
}

__device__ __forceinline__ void cp16s(uint32_t dst, const void* src) {
    asm volatile("cp.async.cg.shared.global [%0], [%1], 16;" :: "r"(dst), "l"(src));
}
__device__ __forceinline__ void cp_commit() {
    asm volatile("cp.async.commit_group;");
}
template <int N> __device__ __forceinline__ void cp_wait() {
    asm volatile("cp.async.wait_group %0;" :: "n"(N));
}
__device__ __forceinline__ uint32_t smem_u32(const void* p) {
    uint32_t a;
    asm("{ .reg .u64 t; cvta.to.shared.u64 t, %1; cvt.u32.u64 %0, t; }"
        : "=r"(a) : "l"(p));
    return a;
}
__device__ __forceinline__ unsigned h2u(__half2 h) {
    return *reinterpret_cast<unsigned*>(&h);
}

// ------- kernel 0: weight convert+transpose fp32 [K][N] -> fp16 [N][K] ------
__global__ __launch_bounds__(256) void wcvt_kernel(
    const float* __restrict__ w, __half* __restrict__ wt, int K, int N)
{
    __shared__ float t[32][33];
    int n0 = blockIdx.x * 32, k0 = blockIdx.y * 32;
    int tx = threadIdx.x & 31, ty = threadIdx.x >> 5;
    #pragma unroll
    for (int j = 0; j < 32; j += 8)
        t[ty + j][tx] = w[(size_t)(k0 + ty + j) * N + n0 + tx];
    __syncthreads();
    #pragma unroll
    for (int j = 0; j < 32; j += 8)
        wt[(size_t)(n0 + ty + j) * K + k0 + tx] = __float2half(t[tx][ty + j]);
}

// ---------------- kernel 1: mod = swish(c) @ w_mod + b_mod ----------------
__global__ __launch_bounds__(128) void mod_kernel(
    const float* __restrict__ c, const float* __restrict__ w_mod,
    const float* __restrict__ b_mod, float* __restrict__ mod)
{
    __shared__ float sc[HID];
    int b = blockIdx.y;
    for (int i = threadIdx.x; i < HID; i += blockDim.x) {
        float v = c[b * HID + i];
        sc[i] = v / (1.0f + expf(-v));
    }
    __syncthreads();
    int col = blockIdx.x * blockDim.x + threadIdx.x;
    float acc = b_mod[col];
    #pragma unroll 4
    for (int k = 0; k < HID; ++k)
        acc = fmaf(sc[k], w_mod[(size_t)k * MODW + col], acc);
    mod[b * MODW + col] = acc;
}

// --------- kernel 2: LN(x) * (1+sc) + sh  (per row), fp16 output ------------
__global__ __launch_bounds__(256) void ln_mod_kernel(
    const float* __restrict__ x, const float* __restrict__ mod,
    int shOff, int scOff, __half* __restrict__ out)
{
    __shared__ float buf[HID];
    __shared__ float red[16];
    int row = blockIdx.x;
    int b = row >> 10;
    int tid = threadIdx.x;
    const float* xr = x + (size_t)row * HID;
    float s = 0.f, s2 = 0.f;
    for (int i = tid; i < 288; i += 256) {       // 288 float4 = 1152
        float4 v = *(const float4*)(xr + i * 4);
        *(float4*)(buf + i * 4) = v;
        s  += v.x + v.y + v.z + v.w;
        s2 += v.x * v.x + v.y * v.y + v.z * v.z + v.w * v.w;
    }
    #pragma unroll
    for (int o = 16; o; o >>= 1) {
        s  += __shfl_xor_sync(0xffffffffu, s,  o);
        s2 += __shfl_xor_sync(0xffffffffu, s2, o);
    }
    if ((tid & 31) == 0) { red[tid >> 5] = s; red[8 + (tid >> 5)] = s2; }
    __syncthreads();
    float S = 0.f, S2 = 0.f;
    #pragma unroll
    for (int w = 0; w < 8; ++w) { S += red[w]; S2 += red[8 + w]; }
    float mean = S * (1.f / HID);
    float var  = S2 * (1.f / HID) - mean * mean;
    float rstd = rsqrtf(var + EPS);
    const float* mrow = mod + b * MODW;
    __half* orow = out + (size_t)row * HID;
    for (int i = tid; i < 288; i += 256) {
        float4 v   = *(const float4*)(buf + i * 4);
        float4 sc4 = *(const float4*)(mrow + scOff + i * 4);
        float4 sh4 = *(const float4*)(mrow + shOff + i * 4);
        float o0 = fmaf((v.x - mean) * rstd, 1.f + sc4.x, sh4.x);
        float o1 = fmaf((v.y - mean) * rstd, 1.f + sc4.y, sh4.y);
        float o2 = fmaf((v.z - mean) * rstd, 1.f + sc4.z, sh4.z);
        float o3 = fmaf((v.w - mean) * rstd, 1.f + sc4.w, sh4.w);
        uint2 pk;
        pk.x = h2u(__floats2half2_rn(o0, o1));
        pk.y = h2u(__floats2half2_rn(o2, o3));
        *(uint2*)(orow + i * 4) = pk;
    }
}

// --------------- kernel 3: per-head LN of q and k (fp16, half2) -------------
__global__ __launch_bounds__(256) void qkln_kernel(
    __half* __restrict__ qkv, const float* __restrict__ g_q,
    const float* __restrict__ g_k)
{
    int warp = blockIdx.x * 8 + (threadIdx.x >> 5);
    int lane = threadIdx.x & 31;
    int h  = warp & 15;
    int qk = (warp >> 4) & 1;
    int bn = warp >> 5;
    __half2* p2 = (__half2*)(qkv + (size_t)bn * (3 * HID) + qk * HID + h * HD);
    float2 va = __half22float2(p2[lane]);                // halves 2l, 2l+1
    float2 vb = (lane < 4) ? __half22float2(p2[32 + lane]) : make_float2(0.f, 0.f);
    float s  = va.x + va.y + vb.x + vb.y;
    float s2 = va.x * va.x + va.y * va.y + vb.x * vb.x + vb.y * vb.y;
    #pragma unroll
    for (int o = 16; o; o >>= 1) {
        s  += __shfl_xor_sync(0xffffffffu, s,  o);
        s2 += __shfl_xor_sync(0xffffffffu, s2, o);
    }
    float mean = s * (1.f / HD);
    float var  = s2 * (1.f / HD) - mean * mean;
    float rstd = rsqrtf(var + EPS);
    const float* g = qk ? g_k : g_q;
    float2 ga = *(const float2*)(g + 2 * lane);
    p2[lane] = __floats2half2_rn((va.x - mean) * rstd * ga.x,
                                 (va.y - mean) * rstd * ga.y);
    if (lane < 4) {
        float2 gb = *(const float2*)(g + 64 + 2 * lane);
        p2[32 + lane] = __floats2half2_rn((vb.x - mean) * rstd * gb.x,
                                          (vb.y - mean) * rstd * gb.y);
    }
}

// --------------- kernel 4: flash attention (fp16 mma, FA2 repack) -----------
#define AQ 128
#define AK 64
#define QH 88     // halves stride for qs/ks
#define VH 72     // halves stride for vst (dim-major)
#define ATTN_SMEM ((AQ * QH + AK * QH + HD * VH) * 2)

__global__ __launch_bounds__(256) void attn_kernel(
    const __half* __restrict__ qkv, __half* __restrict__ o)
{
    extern __shared__ __half smh[];
    __half* qs  = smh;                 // [128][88]
    __half* ks  = qs + AQ * QH;        // [64][88]
    __half* vst = ks + AK * QH;        // [72][72]

    int tid = threadIdx.x;
    int lane = tid & 31;
    int warp = tid >> 5;
    int grp = lane >> 2;
    int t4 = lane & 3;
    int m0 = warp * 16;

    int q0 = blockIdx.x * AQ;
    int h = blockIdx.y, b = blockIdx.z;
    const size_t baseBN = (size_t)b * SEQ * (3 * HID);
    const int hoff = h * HD;
    const float scale = 0.11785113019775793f;

    for (int idx = tid; idx < AQ * 9; idx += 256) {
        int r = idx / 9, c = (idx - r * 9) * 8;
        *(float4*)(qs + r * QH + c) =
            *(const float4*)(qkv + baseBN + (size_t)(q0 + r) * (3 * HID) + hoff + c);
    }
    for (int idx = tid; idx < AQ + AK; idx += 256) {
        __half* base = (idx < AQ) ? (qs + idx * QH) : (ks + (idx - AQ) * QH);
        *(float4*)(base + 72) = make_float4(0.f, 0.f, 0.f, 0.f);
    }

    float accO[9][4];
    #pragma unroll
    for (int di = 0; di < 9; ++di)
        #pragma unroll
        for (int e = 0; e < 4; ++e) accO[di][e] = 0.f;
    float mi0 = -INFINITY, mi1 = -INFINITY;
    float li0 = 0.f, li1 = 0.f;

    for (int kt = 0; kt < SEQ / AK; ++kt) {
        __syncthreads();
        int k0 = kt * AK;
        for (int idx = tid; idx < AK * 9; idx += 256) {
            int r = idx / 9, c = (idx - r * 9) * 8;
            *(float4*)(ks + r * QH + c) = *(const float4*)(
                qkv + baseBN + (size_t)(k0 + r) * (3 * HID) + HID + hoff + c);
        }
        for (int idx = tid; idx < AK * 36; idx += 256) {
            int key = idx / 36, d2 = (idx - key * 36) * 2;
            __half2 v = *(const __half2*)(
                qkv + baseBN + (size_t)(k0 + key) * (3 * HID) + 2 * HID + hoff + d2);
            vst[d2 * VH + key]       = __low2half(v);
            vst[(d2 + 1) * VH + key] = __high2half(v);
        }
        __syncthreads();

        float sacc[8][4];
        #pragma unroll
        for (int ni = 0; ni < 8; ++ni)
            #pragma unroll
            for (int e = 0; e < 4; ++e) sacc[ni][e] = 0.f;
        #pragma unroll
        for (int ksb = 0; ksb < 5; ++ksb) {
            int k16 = ksb * 16;
            unsigned a0 = *(const unsigned*)(qs + (m0 + grp) * QH + k16 + t4 * 2);
            unsigned a1 = *(const unsigned*)(qs + (m0 + grp + 8) * QH + k16 + t4 * 2);
            unsigned a2 = *(const unsigned*)(qs + (m0 + grp) * QH + k16 + t4 * 2 + 8);
            unsigned a3 = *(const unsigned*)(qs + (m0 + grp + 8) * QH + k16 + t4 * 2 + 8);
            #pragma unroll
            for (int ni = 0; ni < 8; ++ni) {
                unsigned b0 = *(const unsigned*)(ks + (ni * 8 + grp) * QH + k16 + t4 * 2);
                unsigned b1 = *(const unsigned*)(ks + (ni * 8 + grp) * QH + k16 + t4 * 2 + 8);
                mma_f16(sacc[ni][0], sacc[ni][1], sacc[ni][2], sacc[ni][3],
                        a0, a1, a2, a3, b0, b1);
            }
        }

        float rmax0 = -INFINITY, rmax1 = -INFINITY;
        #pragma unroll
        for (int ni = 0; ni < 8; ++ni) {
            sacc[ni][0] *= scale; sacc[ni][1] *= scale;
            sacc[ni][2] *= scale; sacc[ni][3] *= scale;
            rmax0 = fmaxf(rmax0, fmaxf(sacc[ni][0], sacc[ni][1]));
            rmax1 = fmaxf(rmax1, fmaxf(sacc[ni][2], sacc[ni][3]));
        }
        #pragma unroll
        for (int off = 1; off < 4; off <<= 1) {
            rmax0 = fmaxf(rmax0, __shfl_xor_sync(0xffffffffu, rmax0, off));
            rmax1 = fmaxf(rmax1, __shfl_xor_sync(0xffffffffu, rmax1, off));
        }
        float newm0 = fmaxf(mi0, rmax0);
        float newm1 = fmaxf(mi1, rmax1);
        float alpha0 = __expf(mi0 - newm0);
        float alpha1 = __expf(mi1 - newm1);
        mi0 = newm0; mi1 = newm1;
        float rsum0 = 0.f, rsum1 = 0.f;
        unsigned ph0[8], ph1[8];
        #pragma unroll
        for (int ni = 0; ni < 8; ++ni) {
            float p0 = __expf(sacc[ni][0] - newm0);
            float p1 = __expf(sacc[ni][1] - newm0);
            float p2 = __expf(sacc[ni][2] - newm1);
            float p3 = __expf(sacc[ni][3] - newm1);
            rsum0 += p0 + p1; rsum1 += p2 + p3;
            ph0[ni] = h2u(__floats2half2_rn(p0, p1));
            ph1[ni] = h2u(__floats2half2_rn(p2, p3));
        }
        #pragma unroll
        for (int off = 1; off < 4; off <<= 1) {
            rsum0 += __shfl_xor_sync(0xffffffffu, rsum0, off);
            rsum1 += __shfl_xor_sync(0xffffffffu, rsum1, off);
        }
        li0 = li0 * alpha0 + rsum0;
        li1 = li1 * alpha1 + rsum1;
        #pragma unroll
        for (int di = 0; di < 9; ++di) {
            accO[di][0] *= alpha0; accO[di][1] *= alpha0;
            accO[di][2] *= alpha1; accO[di][3] *= alpha1;
        }

        #pragma unroll
        for (int kb = 0; kb < 4; ++kb) {
            unsigned a0 = ph0[2 * kb],     a2 = ph0[2 * kb + 1];
            unsigned a1 = ph1[2 * kb],     a3 = ph1[2 * kb + 1];
            #pragma unroll
            for (int di = 0; di < 9; ++di) {
                unsigned b0 = *(const unsigned*)(vst + (di * 8 + grp) * VH + kb * 16 + t4 * 2);
                unsigned b1 = *(const unsigned*)(vst + (di * 8 + grp) * VH + kb * 16 + t4 * 2 + 8);
                mma_f16(accO[di][0], accO[di][1], accO[di][2], accO[di][3],
                        a0, a1, a2, a3, b0, b1);
            }
        }
    }

    float inv0 = 1.f / li0, inv1 = 1.f / li1;
    int row0 = q0 + m0 + grp;
    size_t b0a = ((size_t)b * SEQ + row0) * HID + hoff;
    size_t b1a = ((size_t)b * SEQ + row0 + 8) * HID + hoff;
    #pragma unroll
    for (int di = 0; di < 9; ++di) {
        int d = di * 8 + t4 * 2;
        *(__half2*)(o + b0a + d) = __floats2half2_rn(accO[di][0] * inv0, accO[di][1] * inv0);
        *(__half2*)(o + b1a + d) = __floats2half2_rn(accO[di][2] * inv1, accO[di][3] * inv1);
    }
}

// --------------- kernel 5: FP16 GEMM, ldmatrix + TBK=64, 3 stages -----------
#define TBK 64
#define ASTRH 72                          // halves per smem row (64 + 8 pad)
#define TILE_H_BYTES (128 * ASTRH * 2)    // 18432
#define NSTAGE 3
#define GEMM_SMEM (NSTAGE * 2 * TILE_H_BYTES)   // 110592

template <int EPI, typename OutT>
__global__ __launch_bounds__(256) void hgemm_kernel(
    const __half* __restrict__ A, const __half* __restrict__ BT,
    const float* __restrict__ bias, const float* __restrict__ res,
    const float* __restrict__ gate, OutT* __restrict__ C,
    int M, int N, int K)
{
    extern __shared__ char smc[];
    uint32_t sbase = smem_u32(smc);

    int tid = threadIdx.x;
    int lane = tid & 31;
    int warp = tid >> 5;
    int m0 = (warp & 1) * 64;
    int n0 = (warp >> 1) * 32;
    int grp = lane >> 2;
    int t4 = lane & 3;
    int lsel = lane & 15;            // ldmatrix row-select
    int ksel = (lane >> 4) * 8;      // ldmatrix k-half select

    int cRow = blockIdx.y, cCol = blockIdx.x;
    const __half* Ab = A + (size_t)cRow * 128 * K;
    const __half* Bb = BT + (size_t)cCol * 128 * K;

    float acc[4][4][4];
    #pragma unroll
    for (int mi = 0; mi < 4; ++mi)
        #pragma unroll
        for (int ni = 0; ni < 4; ++ni)
            #pragma unroll
            for (int e = 0; e < 4; ++e) acc[mi][ni][e] = 0.f;

    int KT = K / TBK;    // 18 or 72

    // stage loader: A 128x64 halves = 1024 16B-chunks; 4+4 cp.async/thread
    auto load_stage = [&](int kt, int s) {
        uint32_t aBase = sbase + s * TILE_H_BYTES;
        uint32_t bBase = sbase + (NSTAGE + s) * TILE_H_BYTES;
        const __half* Asrc = Ab + kt * TBK;
        const __half* Bsrc = Bb + kt * TBK;
        #pragma unroll
        for (int j = 0; j < 4; ++j) {
            int idx = tid + j * 256;
            int r = idx >> 3, c = idx & 7;
            cp16s(aBase + r * (ASTRH * 2) + c * 16, Asrc + (size_t)r * K + c * 8);
            cp16s(bBase + r * (ASTRH * 2) + c * 16, Bsrc + (size_t)r * K + c * 8);
        }
    };

    #pragma unroll
    for (int s = 0; s < NSTAGE - 1; ++s) {
        load_stage(s, s);
        cp_commit();
    }

    for (int kt = 0; kt < KT; ++kt) {
        cp_wait<NSTAGE - 2>();
        __syncthreads();

        int pf = kt + NSTAGE - 1;
        if (pf < KT) load_stage(pf, pf % NSTAGE);
        cp_commit();

        int st = kt % NSTAGE;
        uint32_t aBase = sbase + st * TILE_H_BYTES;
        uint32_t bBase = sbase + (NSTAGE + st) * TILE_H_BYTES;
        #pragma unroll
        for (int ks = 0; ks < 4; ++ks) {
            int k16 = ks * 16;
            unsigned af[4][4], bf[4][2];
            #pragma unroll
            for (int mi = 0; mi < 4; ++mi)
                ldsm_x4(af[mi][0], af[mi][1], af[mi][2], af[mi][3],
                        aBase + ((m0 + mi * 16 + lsel) * ASTRH + k16 + ksel) * 2);
            ldsm_x4(bf[0][0], bf[1][0], bf[0][1], bf[1][1],
                    bBase + ((n0 + lsel) * ASTRH + k16 + ksel) * 2);
            ldsm_x4(bf[2][0], bf[3][0], bf[2][1], bf[3][1],
                    bBase + ((n0 + 16 + lsel) * ASTRH + k16 + ksel) * 2);
            #pragma unroll
            for (int mi = 0; mi < 4; ++mi)
                #pragma unroll
                for (int ni = 0; ni < 4; ++ni)
                    mma_f16(acc[mi][ni][0], acc[mi][ni][1], acc[mi][ni][2], acc[mi][ni][3],
                            af[mi][0], af[mi][1], af[mi][2], af[mi][3],
                            bf[ni][0], bf[ni][1]);
        }
    }

    // ---- epilogue ----
    #pragma unroll
    for (int mi = 0; mi < 4; ++mi) {
        #pragma unroll
        for (int half_ = 0; half_ < 2; ++half_) {
            int row = cRow * 128 + m0 + mi * 16 + grp + half_ * 8;
            int gb = (row >> 10) * MODW;
            #pragma unroll
            for (int ni = 0; ni < 4; ++ni) {
                int col = cCol * 128 + n0 + ni * 8 + t4 * 2;
                float v0 = acc[mi][ni][half_ * 2 + 0] + bias[col];
                float v1 = acc[mi][ni][half_ * 2 + 1] + bias[col + 1];
                if (EPI == 1) {
                    float i0 = 0.7978845608028654f * (v0 + 0.044715f * v0 * v0 * v0);
                    float i1 = 0.7978845608028654f * (v1 + 0.044715f * v1 * v1 * v1);
                    v0 = v0 / (1.f + __expf(-2.f * i0));
                    v1 = v1 / (1.f + __expf(-2.f * i1));
                } else if (EPI == 2) {
                    v0 = fmaf(gate[gb + col],     v0, res[(size_t)row * N + col]);
                    v1 = fmaf(gate[gb + col + 1], v1, res[(size_t)row * N + col + 1]);
                }
                OutT* dst = C + (size_t)row * N + col;
                if (sizeof(OutT) == 2) {
                    *(__half2*)dst = __floats2half2_rn(v0, v1);
                } else {
                    *(float2*)dst = make_float2(v0, v1);
                }
            }
        }
    }
}

// ---------------------------- launcher --------------------------------------
extern "C" void kernel_launch(void* const* d_in, const int* in_sizes, int n_in,
                              void* d_out, int out_size)
{
    const float* x      = (const float*)d_in[0];
    const float* c      = (const float*)d_in[1];
    const float* w_mod  = (const float*)d_in[2];
    const float* b_mod  = (const float*)d_in[3];
    const float* w_qkv  = (const float*)d_in[4];
    const float* b_qkv  = (const float*)d_in[5];
    const float* gq     = (const float*)d_in[6];
    const float* gk     = (const float*)d_in[7];
    const float* w_proj = (const float*)d_in[8];
    const float* b_proj = (const float*)d_in[9];
    const float* w1     = (const float*)d_in[10];
    const float* b1     = (const float*)d_in[11];
    const float* w2     = (const float*)d_in[12];
    const float* b2     = (const float*)d_in[13];
    float* out = (float*)d_out;

    float *p_mod, *p_x1;
    __half *p_xn16, *p_qkv16, *p_o16, *p_h16, *p_wqkvT, *p_wprojT, *p_w1T, *p_w2T;
    cudaGetSymbolAddress((void**)&p_mod, g_mod);
    cudaGetSymbolAddress((void**)&p_xn16, g_xn16);
    cudaGetSymbolAddress((void**)&p_qkv16, g_qkv16);
    cudaGetSymbolAddress((void**)&p_o16, g_o16);
    cudaGetSymbolAddress((void**)&p_x1,  g_x1);
    cudaGetSymbolAddress((void**)&p_h16, g_h16);
    cudaGetSymbolAddress((void**)&p_wqkvT, g_wqkvT16);
    cudaGetSymbolAddress((void**)&p_wprojT, g_wprojT16);
    cudaGetSymbolAddress((void**)&p_w1T, g_w1T16);
    cudaGetSymbolAddress((void**)&p_w2T, g_w2T16);

    cudaFuncSetAttribute(attn_kernel,
                         cudaFuncAttributeMaxDynamicSharedMemorySize, ATTN_SMEM);
    cudaFuncSetAttribute(hgemm_kernel<0, __half>,
                         cudaFuncAttributeMaxDynamicSharedMemorySize, GEMM_SMEM);
    cudaFuncSetAttribute(hgemm_kernel<1, __half>,
                         cudaFuncAttributeMaxDynamicSharedMemorySize, GEMM_SMEM);
    cudaFuncSetAttribute(hgemm_kernel<2, float>,
                         cudaFuncAttributeMaxDynamicSharedMemorySize, GEMM_SMEM);

    // 0. convert+transpose weights to fp16 [N][K]
    wcvt_kernel<<<dim3(3 * HID / 32, HID / 32), 256>>>(w_qkv, p_wqkvT, HID, 3 * HID);
    wcvt_kernel<<<dim3(HID / 32, HID / 32), 256>>>(w_proj, p_wprojT, HID, HID);
    wcvt_kernel<<<dim3(MLPD / 32, HID / 32), 256>>>(w1, p_w1T, HID, MLPD);
    wcvt_kernel<<<dim3(HID / 32, MLPD / 32), 256>>>(w2, p_w2T, MLPD, HID);

    // 1. adaLN modulation
    mod_kernel<<<dim3(MODW / 128, Bsz), 128>>>(c, w_mod, b_mod, p_mod);
    // 2. LN + modulate (MSA) -> fp16
    ln_mod_kernel<<<ROWS, 256>>>(x, p_mod, 0, HID, p_xn16);
    // 3. QKV GEMM -> fp16 qkv
    hgemm_kernel<0, __half><<<dim3(3 * HID / 128, ROWS / 128), 256, GEMM_SMEM>>>(
        p_xn16, p_wqkvT, b_qkv, nullptr, nullptr, p_qkv16, ROWS, 3 * HID, HID);
    // 4. per-head LN of q,k
    qkln_kernel<<<ROWS * 32 / 8, 256>>>(p_qkv16, gq, gk);
    // 5. attention -> fp16 o
    attn_kernel<<<dim3(SEQ / AQ, NH, Bsz), 256, ATTN_SMEM>>>(p_qkv16, p_o16);
    // 6. proj + gated residual -> fp32 x1
    hgemm_kernel<2, float><<<dim3(HID / 128, ROWS / 128), 256, GEMM_SMEM>>>(
        p_o16, p_wprojT, b_proj, x, p_mod + 2 * HID, p_x1, ROWS, HID, HID);
    // 7. LN + modulate (MLP) -> fp16
    ln_mod_kernel<<<ROWS, 256>>>(p_x1, p_mod, 3 * HID, 4 * HID, p_xn16);
    // 8. MLP up + gelu -> fp16 h
    hgemm_kernel<1, __half><<<dim3(MLPD / 128, ROWS / 128), 256, GEMM_SMEM>>>(
        p_xn16, p_w1T, b1, nullptr, nullptr, p_h16, ROWS, MLPD, HID);
    // 9. MLP down + gated residual -> fp32 out
    hgemm_kernel<2, float><<<dim3(HID / 128, ROWS / 128), 256, GEMM_SMEM>>>(
        p_h16, p_w2T, b2, p_x1, p_mod + 5 * HID, out, ROWS, HID, MLPD);
}